// round 2
// baseline (speedup 1.0000x reference)
#include <cuda_runtime.h>
#include <math.h>

#define BATCH 2
#define TSEQ 2048
#define DMODEL 2048
#define NHEAD 16
#define DHEAD 128
#define MTOT (BATCH*TSEQ)   // 4096

// Scratch (allocation-free rule: __device__ globals)
__device__ float g_Q[BATCH*TSEQ*DMODEL];
__device__ float g_K[BATCH*TSEQ*DMODEL];
__device__ float g_V[BATCH*TSEQ*DMODEL];
__device__ float g_C[BATCH*TSEQ*DMODEL];

// ---------------------------------------------------------------------------
// Generic fp32 SGEMM: C[M,N] = A[M,K] @ B[K,N], 128x128 tile, BK=8, 256 thr
// ---------------------------------------------------------------------------
__global__ __launch_bounds__(256) void sgemm_kernel(
    const float* __restrict__ A, const float* __restrict__ Bm,
    float* __restrict__ C, int M, int N, int K)
{
    __shared__ float As[8][128];
    __shared__ float Bs[8][128];
    const int tid = threadIdx.x;
    const int tx = tid & 15, ty = tid >> 4;
    const int bx = blockIdx.x, by = blockIdx.y;
    const float* Ab = A + (size_t)by * 128 * K;
    const float* Bb = Bm + (size_t)bx * 128;
    const int arow = tid >> 1, acol = (tid & 1) * 4;
    const int brow = tid >> 5, bcol = (tid & 31) * 4;

    float acc[8][8];
#pragma unroll
    for (int i = 0; i < 8; i++)
#pragma unroll
        for (int j = 0; j < 8; j++) acc[i][j] = 0.f;

    for (int k0 = 0; k0 < K; k0 += 8) {
        float4 a4 = *(const float4*)(Ab + (size_t)arow * K + k0 + acol);
        As[acol + 0][arow] = a4.x;
        As[acol + 1][arow] = a4.y;
        As[acol + 2][arow] = a4.z;
        As[acol + 3][arow] = a4.w;
        *(float4*)&Bs[brow][bcol] =
            *(const float4*)(Bb + (size_t)(k0 + brow) * N + bcol);
        __syncthreads();
#pragma unroll
        for (int k = 0; k < 8; k++) {
            float4 a0 = *(float4*)&As[k][ty * 4];
            float4 a1 = *(float4*)&As[k][64 + ty * 4];
            float4 b0 = *(float4*)&Bs[k][tx * 4];
            float4 b1 = *(float4*)&Bs[k][64 + tx * 4];
            float a[8] = {a0.x, a0.y, a0.z, a0.w, a1.x, a1.y, a1.z, a1.w};
            float b[8] = {b0.x, b0.y, b0.z, b0.w, b1.x, b1.y, b1.z, b1.w};
#pragma unroll
            for (int i = 0; i < 8; i++)
#pragma unroll
                for (int j = 0; j < 8; j++)
                    acc[i][j] = fmaf(a[i], b[j], acc[i][j]);
        }
        __syncthreads();
    }

    float* Cb = C + (size_t)by * 128 * N + bx * 128;
#pragma unroll
    for (int ih = 0; ih < 2; ih++) {
#pragma unroll
        for (int i = 0; i < 4; i++) {
            int r = ih * 64 + ty * 4 + i;
            float4 v0 = make_float4(acc[ih*4+i][0], acc[ih*4+i][1],
                                    acc[ih*4+i][2], acc[ih*4+i][3]);
            float4 v1 = make_float4(acc[ih*4+i][4], acc[ih*4+i][5],
                                    acc[ih*4+i][6], acc[ih*4+i][7]);
            *(float4*)(Cb + (size_t)r * N + tx * 4)      = v0;
            *(float4*)(Cb + (size_t)r * N + 64 + tx * 4) = v1;
        }
    }
}

// ---------------------------------------------------------------------------
// RoPE (in place, on both Q and K buffers). Layout [b][t][h*128 + j].
// rotate-half: (x1,x2)=(v[j], v[j+64]); out = (x1 c - x2 s, x1 s + x2 c)
// ---------------------------------------------------------------------------
__global__ void rope_kernel(float* __restrict__ Q, float* __restrict__ K,
                            const int* __restrict__ posp)
{
    const int total = BATCH * TSEQ * NHEAD * 64;  // per tensor
    int idx = blockIdx.x * blockDim.x + threadIdx.x;
    if (idx >= 2 * total) return;
    float* buf = (idx < total) ? Q : K;
    int e = (idx < total) ? idx : idx - total;
    int j = e & 63;
    int h = (e >> 6) & (NHEAD - 1);
    int t = (e >> 10) & (TSEQ - 1);
    int b = e >> 21;
    int p0 = *posp; if (p0 < 0) p0 = 0;
    // inv_freq = 10000^(-j/64) = exp(-j * ln(10000)/64)
    float inv = __expf(-0.14391156463f * (float)j);
    float ang = (float)(p0 + t) * inv;
    float s, c;
    sincosf(ang, &s, &c);
    size_t base = ((size_t)(b * TSEQ + t)) * DMODEL + h * DHEAD + j;
    float x1 = buf[base], x2 = buf[base + 64];
    buf[base]      = x1 * c - x2 * s;
    buf[base + 64] = x1 * s + x2 * c;
}

// ---------------------------------------------------------------------------
// Flash attention, fp32. One block = (64 queries) x (one b,h). 256 threads.
// smem: Qs/Ks/Vs 64x132 (padded), Ss 64x65.
// ---------------------------------------------------------------------------
#define BQ 64
#define KP 132
#define SP 65

__global__ __launch_bounds__(256) void attn_kernel(
    const float* __restrict__ Q, const float* __restrict__ Kt,
    const float* __restrict__ V, float* __restrict__ Cc)
{
    extern __shared__ float sm[];
    float* Qs = sm;                // 64*132
    float* Ks = Qs + BQ * KP;
    float* Vs = Ks + BQ * KP;
    float* Ss = Vs + BQ * KP;      // 64*65

    const int tid  = threadIdx.x;
    const int lane = tid & 31, w = tid >> 5;
    const int tx   = tid & 15, ty = tid >> 4;
    const int qb = blockIdx.x;
    const int bh = blockIdx.y;
    const int b = bh >> 4, h = bh & (NHEAD - 1);
    const float scale = 0.08838834764831845f;  // 1/sqrt(128)
    const size_t rowbase = (size_t)b * TSEQ + (size_t)qb * BQ;

    // load Q tile, pre-scaled
    for (int i = tid; i < BQ * 32; i += 256) {
        int r = i >> 5, c4 = (i & 31) * 4;
        float4 q = *(const float4*)(Q + (rowbase + r) * DMODEL + h * DHEAD + c4);
        q.x *= scale; q.y *= scale; q.z *= scale; q.w *= scale;
        *(float4*)&Qs[r * KP + c4] = q;
    }

    float O[8][4];
    float m[8], l[8];
#pragma unroll
    for (int i = 0; i < 8; i++) {
        m[i] = -1e30f; l[i] = 0.f;
        O[i][0] = O[i][1] = O[i][2] = O[i][3] = 0.f;
    }

    for (int kb = 0; kb <= qb; kb++) {
        __syncthreads();  // prior-iter consumers done (also orders Qs on iter 0)
        size_t kbase = (size_t)b * TSEQ + (size_t)kb * BQ;
        for (int i = tid; i < BQ * 32; i += 256) {
            int r = i >> 5, c4 = (i & 31) * 4;
            *(float4*)&Ks[r * KP + c4] =
                *(const float4*)(Kt + (kbase + r) * DMODEL + h * DHEAD + c4);
            *(float4*)&Vs[r * KP + c4] =
                *(const float4*)(V + (kbase + r) * DMODEL + h * DHEAD + c4);
        }
        __syncthreads();

        // S = Qs @ Ks^T : thread -> rows {ty+16i}, cols {tx+16j}
        float acc[4][4];
#pragma unroll
        for (int i = 0; i < 4; i++)
#pragma unroll
            for (int j = 0; j < 4; j++) acc[i][j] = 0.f;

        for (int k = 0; k < DHEAD; k += 4) {
            float4 a[4], bb[4];
#pragma unroll
            for (int i = 0; i < 4; i++) a[i]  = *(float4*)&Qs[(ty + 16 * i) * KP + k];
#pragma unroll
            for (int j = 0; j < 4; j++) bb[j] = *(float4*)&Ks[(tx + 16 * j) * KP + k];
#pragma unroll
            for (int i = 0; i < 4; i++)
#pragma unroll
                for (int j = 0; j < 4; j++) {
                    acc[i][j] = fmaf(a[i].x, bb[j].x, acc[i][j]);
                    acc[i][j] = fmaf(a[i].y, bb[j].y, acc[i][j]);
                    acc[i][j] = fmaf(a[i].z, bb[j].z, acc[i][j]);
                    acc[i][j] = fmaf(a[i].w, bb[j].w, acc[i][j]);
                }
        }

        // causal mask + store scores
#pragma unroll
        for (int i = 0; i < 4; i++) {
            int r = ty + 16 * i;
            int qglob = qb * BQ + r;
#pragma unroll
            for (int j = 0; j < 4; j++) {
                int cidx = tx + 16 * j;
                int kglob = kb * BQ + cidx;
                Ss[r * SP + cidx] = (kglob <= qglob) ? acc[i][j] : -1e30f;
            }
        }
        __syncthreads();

        // online softmax: warp w owns rows w*8 .. w*8+7
#pragma unroll
        for (int i = 0; i < 8; i++) {
            int r = w * 8 + i;
            float s0 = Ss[r * SP + lane];
            float s1 = Ss[r * SP + lane + 32];
            float tmax = fmaxf(s0, s1);
#pragma unroll
            for (int off = 16; off; off >>= 1)
                tmax = fmaxf(tmax, __shfl_xor_sync(0xffffffffu, tmax, off));
            float mnew = fmaxf(m[i], tmax);
            float p0 = __expf(s0 - mnew);
            float p1 = __expf(s1 - mnew);
            Ss[r * SP + lane]      = p0;
            Ss[r * SP + lane + 32] = p1;
            float alpha = __expf(m[i] - mnew);
            float ps = p0 + p1;
#pragma unroll
            for (int off = 16; off; off >>= 1)
                ps += __shfl_xor_sync(0xffffffffu, ps, off);
            l[i] = l[i] * alpha + ps;
            m[i] = mnew;
            O[i][0] *= alpha; O[i][1] *= alpha;
            O[i][2] *= alpha; O[i][3] *= alpha;
        }
        __syncwarp();

        // O += P @ V (lane owns cols lane*4..lane*4+3)
        for (int k = 0; k < BQ; k++) {
            float4 v = *(float4*)&Vs[k * KP + lane * 4];
#pragma unroll
            for (int i = 0; i < 8; i++) {
                float p = Ss[(w * 8 + i) * SP + k];
                O[i][0] = fmaf(p, v.x, O[i][0]);
                O[i][1] = fmaf(p, v.y, O[i][1]);
                O[i][2] = fmaf(p, v.z, O[i][2]);
                O[i][3] = fmaf(p, v.w, O[i][3]);
            }
        }
    }

    // epilogue: normalize and write ctx in [b, t, d] layout
#pragma unroll
    for (int i = 0; i < 8; i++) {
        float inv = 1.0f / l[i];
        int r = w * 8 + i;
        float4 o = make_float4(O[i][0] * inv, O[i][1] * inv,
                               O[i][2] * inv, O[i][3] * inv);
        *(float4*)(Cc + (rowbase + r) * DMODEL + h * DHEAD + lane * 4) = o;
    }
}

// ---------------------------------------------------------------------------
extern "C" void kernel_launch(void* const* d_in, const int* in_sizes, int n_in,
                              void* d_out, int out_size)
{
    const float* x  = (const float*)d_in[0];
    const float* qw = (const float*)d_in[1];
    const float* kw = (const float*)d_in[2];
    const float* vw = (const float*)d_in[3];
    const float* ww = (const float*)d_in[4];
    const int* pos  = (const int*)d_in[5];
    float* out = (float*)d_out;

    float *Qb, *Kb, *Vb, *Cb;
    cudaGetSymbolAddress((void**)&Qb, g_Q);
    cudaGetSymbolAddress((void**)&Kb, g_K);
    cudaGetSymbolAddress((void**)&Vb, g_V);
    cudaGetSymbolAddress((void**)&Cb, g_C);

    dim3 gg(DMODEL / 128, MTOT / 128);
    sgemm_kernel<<<gg, 256>>>(x, qw, Qb, MTOT, DMODEL, DMODEL);
    sgemm_kernel<<<gg, 256>>>(x, kw, Kb, MTOT, DMODEL, DMODEL);
    sgemm_kernel<<<gg, 256>>>(x, vw, Vb, MTOT, DMODEL, DMODEL);

    int ropeN = 2 * BATCH * TSEQ * NHEAD * 64;
    rope_kernel<<<(ropeN + 255) / 256, 256>>>(Qb, Kb, pos);

    size_t smem = (size_t)(3 * BQ * KP + BQ * SP) * sizeof(float);
    cudaFuncSetAttribute(attn_kernel,
                         cudaFuncAttributeMaxDynamicSharedMemorySize, (int)smem);
    dim3 ga(TSEQ / BQ, BATCH * NHEAD);
    attn_kernel<<<ga, 256, smem>>>(Qb, Kb, Vb, Cb);

    sgemm_kernel<<<gg, 256>>>(Cb, ww, out, MTOT, DMODEL, DMODEL);
}

// round 8
// speedup vs baseline: 2.2648x; 2.2648x over previous
#include <cuda_runtime.h>
#include <cuda_bf16.h>
#include <mma.h>
#include <math.h>

#define BATCH 2
#define TSEQ 2048
#define DMODEL 2048
#define NHEAD 16
#define DHEAD 128
#define MTOT (BATCH*TSEQ)

// ---------------- scratch (__device__ globals; no allocs allowed) ----------
__device__ float g_Q[MTOT*DMODEL];
__device__ float g_K[MTOT*DMODEL];
__device__ float g_V[MTOT*DMODEL];
__device__ float g_C[MTOT*DMODEL];

__device__ __nv_bfloat16 g_xhi[MTOT*DMODEL];
__device__ __nv_bfloat16 g_xlo[MTOT*DMODEL];
__device__ __nv_bfloat16 g_chi[MTOT*DMODEL];
__device__ __nv_bfloat16 g_clo[MTOT*DMODEL];
__device__ __nv_bfloat16 g_wqhi[DMODEL*DMODEL];
__device__ __nv_bfloat16 g_wqlo[DMODEL*DMODEL];
__device__ __nv_bfloat16 g_wkhi[DMODEL*DMODEL];
__device__ __nv_bfloat16 g_wklo[DMODEL*DMODEL];
__device__ __nv_bfloat16 g_wvhi[DMODEL*DMODEL];
__device__ __nv_bfloat16 g_wvlo[DMODEL*DMODEL];
__device__ __nv_bfloat16 g_wohi[DMODEL*DMODEL];
__device__ __nv_bfloat16 g_wolo[DMODEL*DMODEL];

// ---------------------------------------------------------------------------
// split fp32 -> bf16 hi + bf16 lo (residual)
// ---------------------------------------------------------------------------
__global__ void split_kernel(const float* __restrict__ in,
                             __nv_bfloat16* __restrict__ hi,
                             __nv_bfloat16* __restrict__ lo, int n4)
{
    int i = blockIdx.x * blockDim.x + threadIdx.x;
    if (i >= n4) return;
    float4 v = ((const float4*)in)[i];
    __nv_bfloat16 h0 = __float2bfloat16_rn(v.x);
    __nv_bfloat16 h1 = __float2bfloat16_rn(v.y);
    __nv_bfloat16 h2 = __float2bfloat16_rn(v.z);
    __nv_bfloat16 h3 = __float2bfloat16_rn(v.w);
    __nv_bfloat16 l0 = __float2bfloat16_rn(v.x - __bfloat162float(h0));
    __nv_bfloat16 l1 = __float2bfloat16_rn(v.y - __bfloat162float(h1));
    __nv_bfloat16 l2 = __float2bfloat16_rn(v.z - __bfloat162float(h2));
    __nv_bfloat16 l3 = __float2bfloat16_rn(v.w - __bfloat162float(h3));
    __nv_bfloat162 ha; ha.x = h0; ha.y = h1;
    __nv_bfloat162 hb; hb.x = h2; hb.y = h3;
    __nv_bfloat162 la; la.x = l0; la.y = l1;
    __nv_bfloat162 lb; lb.x = l2; lb.y = l3;
    ((__nv_bfloat162*)hi)[2*i]   = ha;
    ((__nv_bfloat162*)hi)[2*i+1] = hb;
    ((__nv_bfloat162*)lo)[2*i]   = la;
    ((__nv_bfloat162*)lo)[2*i+1] = lb;
}

// ---------------------------------------------------------------------------
// WMMA 3-term bf16 GEMM: C = Ah*Bh + Ah*Bl + Al*Bh (fp32 accum)
// BM=BN=128, BK=32. 256 threads = 8 warps (4m x 2n), warp tile 32x64.
// Static smem, register-prefetch double buffering. No inline asm.
// ---------------------------------------------------------------------------
#define LDA 40
#define LDB 136

__global__ __launch_bounds__(256) void bf16x3_gemm(
    const __nv_bfloat16* __restrict__ Ah, const __nv_bfloat16* __restrict__ Al,
    const __nv_bfloat16* __restrict__ Bh, const __nv_bfloat16* __restrict__ Bl,
    float* __restrict__ C, int M, int N, int K)
{
    __shared__ __nv_bfloat16 sAh[128*LDA];
    __shared__ __nv_bfloat16 sAl[128*LDA];
    __shared__ __nv_bfloat16 sBh[32*LDB];
    __shared__ __nv_bfloat16 sBl[32*LDB];

    const int tid  = threadIdx.x;
    const int warp = tid >> 5;
    const int wm   = warp >> 1;
    const int wn   = warp & 1;
    const int bx   = blockIdx.x, by = blockIdx.y;

    const __nv_bfloat16* gAh = Ah + (size_t)by * 128 * K;
    const __nv_bfloat16* gAl = Al + (size_t)by * 128 * K;
    const __nv_bfloat16* gBh = Bh + (size_t)bx * 128;
    const __nv_bfloat16* gBl = Bl + (size_t)bx * 128;

    // per-thread load coordinates (two 16B chunks per tensor per stage)
    const int c0 = tid, c1 = tid + 256;
    const int ar0 = c0 >> 2, ak0 = (c0 & 3) * 8;
    const int ar1 = c1 >> 2, ak1 = (c1 & 3) * 8;
    const int bk0 = c0 >> 4, bn0 = (c0 & 15) * 8;
    const int bk1 = c1 >> 4, bn1 = (c1 & 15) * 8;

    nvcuda::wmma::fragment<nvcuda::wmma::accumulator, 16, 16, 16, float> acc[2][4];
#pragma unroll
    for (int i = 0; i < 2; i++) {
#pragma unroll
        for (int j = 0; j < 4; j++) {
            nvcuda::wmma::fill_fragment(acc[i][j], 0.0f);
        }
    }

    // first tile -> smem
    *(float4*)&sAh[ar0*LDA + ak0] = *(const float4*)(gAh + (size_t)ar0 * K + ak0);
    *(float4*)&sAh[ar1*LDA + ak1] = *(const float4*)(gAh + (size_t)ar1 * K + ak1);
    *(float4*)&sAl[ar0*LDA + ak0] = *(const float4*)(gAl + (size_t)ar0 * K + ak0);
    *(float4*)&sAl[ar1*LDA + ak1] = *(const float4*)(gAl + (size_t)ar1 * K + ak1);
    *(float4*)&sBh[bk0*LDB + bn0] = *(const float4*)(gBh + (size_t)bk0 * N + bn0);
    *(float4*)&sBh[bk1*LDB + bn1] = *(const float4*)(gBh + (size_t)bk1 * N + bn1);
    *(float4*)&sBl[bk0*LDB + bn0] = *(const float4*)(gBl + (size_t)bk0 * N + bn0);
    *(float4*)&sBl[bk1*LDB + bn1] = *(const float4*)(gBl + (size_t)bk1 * N + bn1);
    __syncthreads();

    const int NK = K / 32;
    float4 pa0, pa1, pb0, pb1, qa0, qa1, qb0, qb1;

    for (int kt = 0; kt < NK; kt++) {
        const int k0 = (kt + 1) * 32;
        const bool more = (kt + 1 < NK);
        if (more) {
            pa0 = *(const float4*)(gAh + (size_t)ar0 * K + k0 + ak0);
            pa1 = *(const float4*)(gAh + (size_t)ar1 * K + k0 + ak1);
            qa0 = *(const float4*)(gAl + (size_t)ar0 * K + k0 + ak0);
            qa1 = *(const float4*)(gAl + (size_t)ar1 * K + k0 + ak1);
            pb0 = *(const float4*)(gBh + (size_t)(k0 + bk0) * N + bn0);
            pb1 = *(const float4*)(gBh + (size_t)(k0 + bk1) * N + bn1);
            qb0 = *(const float4*)(gBl + (size_t)(k0 + bk0) * N + bn0);
            qb1 = *(const float4*)(gBl + (size_t)(k0 + bk1) * N + bn1);
        }

#pragma unroll
        for (int ks = 0; ks < 2; ks++) {
            nvcuda::wmma::fragment<nvcuda::wmma::matrix_a, 16, 16, 16,
                                   __nv_bfloat16, nvcuda::wmma::row_major> aH[2], aL[2];
#pragma unroll
            for (int i = 0; i < 2; i++) {
                nvcuda::wmma::load_matrix_sync(aH[i],
                    &sAh[(wm*32 + i*16)*LDA + ks*16], LDA);
                nvcuda::wmma::load_matrix_sync(aL[i],
                    &sAl[(wm*32 + i*16)*LDA + ks*16], LDA);
            }
#pragma unroll
            for (int j = 0; j < 4; j++) {
                nvcuda::wmma::fragment<nvcuda::wmma::matrix_b, 16, 16, 16,
                                       __nv_bfloat16, nvcuda::wmma::row_major> bF;
                nvcuda::wmma::load_matrix_sync(bF,
                    &sBh[ks*16*LDB + wn*64 + j*16], LDB);
#pragma unroll
                for (int i = 0; i < 2; i++) {
                    nvcuda::wmma::mma_sync(acc[i][j], aH[i], bF, acc[i][j]);
                    nvcuda::wmma::mma_sync(acc[i][j], aL[i], bF, acc[i][j]);
                }
                nvcuda::wmma::load_matrix_sync(bF,
                    &sBl[ks*16*LDB + wn*64 + j*16], LDB);
#pragma unroll
                for (int i = 0; i < 2; i++) {
                    nvcuda::wmma::mma_sync(acc[i][j], aH[i], bF, acc[i][j]);
                }
            }
        }
        __syncthreads();

        if (more) {
            *(float4*)&sAh[ar0*LDA + ak0] = pa0;
            *(float4*)&sAh[ar1*LDA + ak1] = pa1;
            *(float4*)&sAl[ar0*LDA + ak0] = qa0;
            *(float4*)&sAl[ar1*LDA + ak1] = qa1;
            *(float4*)&sBh[bk0*LDB + bn0] = pb0;
            *(float4*)&sBh[bk1*LDB + bn1] = pb1;
            *(float4*)&sBl[bk0*LDB + bn0] = qb0;
            *(float4*)&sBl[bk1*LDB + bn1] = qb1;
            __syncthreads();
        }
    }

    float* Cb = C + (size_t)(by * 128) * N + bx * 128;
#pragma unroll
    for (int i = 0; i < 2; i++) {
#pragma unroll
        for (int j = 0; j < 4; j++) {
            nvcuda::wmma::store_matrix_sync(
                Cb + (size_t)(wm*32 + i*16) * N + wn*64 + j*16,
                acc[i][j], N, nvcuda::wmma::mem_row_major);
        }
    }
}

// ---------------------------------------------------------------------------
// RoPE (in place on Q and K)
// ---------------------------------------------------------------------------
__global__ void rope_kernel(float* __restrict__ Q, float* __restrict__ K,
                            const int* __restrict__ posp)
{
    const int total = BATCH * TSEQ * NHEAD * 64;
    int idx = blockIdx.x * blockDim.x + threadIdx.x;
    if (idx >= 2 * total) return;
    float* buf = (idx < total) ? Q : K;
    int e = (idx < total) ? idx : idx - total;
    int j = e & 63;
    int h = (e >> 6) & (NHEAD - 1);
    int t = (e >> 10) & (TSEQ - 1);
    int b = e >> 21;
    int p0 = *posp; if (p0 < 0) p0 = 0;
    float inv = __expf(-0.14391156463f * (float)j);
    float ang = (float)(p0 + t) * inv;
    float s, c;
    sincosf(ang, &s, &c);
    size_t base = ((size_t)(b * TSEQ + t)) * DMODEL + h * DHEAD + j;
    float x1 = buf[base], x2 = buf[base + 64];
    buf[base]      = x1 * c - x2 * s;
    buf[base + 64] = x1 * s + x2 * c;
}

// ---------------------------------------------------------------------------
// Flash attention, fp32 (same as R1 pass)
// ---------------------------------------------------------------------------
#define BQ 64
#define KP 132
#define SP 65

__global__ __launch_bounds__(256) void attn_kernel(
    const float* __restrict__ Q, const float* __restrict__ Kt,
    const float* __restrict__ V, float* __restrict__ Cc)
{
    extern __shared__ float smf[];
    float* Qs = smf;
    float* Ks = Qs + BQ * KP;
    float* Vs = Ks + BQ * KP;
    float* Ss = Vs + BQ * KP;

    const int tid  = threadIdx.x;
    const int lane = tid & 31, w = tid >> 5;
    const int tx   = tid & 15, ty = tid >> 4;
    const int qb = blockIdx.x;
    const int bh = blockIdx.y;
    const int b = bh >> 4, h = bh & (NHEAD - 1);
    const float scale = 0.08838834764831845f;
    const size_t rowbase = (size_t)b * TSEQ + (size_t)qb * BQ;

    for (int i = tid; i < BQ * 32; i += 256) {
        int r = i >> 5, c4 = (i & 31) * 4;
        float4 q = *(const float4*)(Q + (rowbase + r) * DMODEL + h * DHEAD + c4);
        q.x *= scale; q.y *= scale; q.z *= scale; q.w *= scale;
        *(float4*)&Qs[r * KP + c4] = q;
    }

    float O[8][4];
    float m[8], l[8];
#pragma unroll
    for (int i = 0; i < 8; i++) {
        m[i] = -1e30f; l[i] = 0.f;
        O[i][0] = O[i][1] = O[i][2] = O[i][3] = 0.f;
    }

    for (int kb = 0; kb <= qb; kb++) {
        __syncthreads();
        size_t kbase = (size_t)b * TSEQ + (size_t)kb * BQ;
        for (int i = tid; i < BQ * 32; i += 256) {
            int r = i >> 5, c4 = (i & 31) * 4;
            *(float4*)&Ks[r * KP + c4] =
                *(const float4*)(Kt + (kbase + r) * DMODEL + h * DHEAD + c4);
            *(float4*)&Vs[r * KP + c4] =
                *(const float4*)(V + (kbase + r) * DMODEL + h * DHEAD + c4);
        }
        __syncthreads();

        float accq[4][4];
#pragma unroll
        for (int i = 0; i < 4; i++) {
#pragma unroll
            for (int j = 0; j < 4; j++) accq[i][j] = 0.f;
        }

        for (int k = 0; k < DHEAD; k += 4) {
            float4 a[4], bb[4];
#pragma unroll
            for (int i = 0; i < 4; i++) a[i]  = *(float4*)&Qs[(ty + 16 * i) * KP + k];
#pragma unroll
            for (int j = 0; j < 4; j++) bb[j] = *(float4*)&Ks[(tx + 16 * j) * KP + k];
#pragma unroll
            for (int i = 0; i < 4; i++) {
#pragma unroll
                for (int j = 0; j < 4; j++) {
                    accq[i][j] = fmaf(a[i].x, bb[j].x, accq[i][j]);
                    accq[i][j] = fmaf(a[i].y, bb[j].y, accq[i][j]);
                    accq[i][j] = fmaf(a[i].z, bb[j].z, accq[i][j]);
                    accq[i][j] = fmaf(a[i].w, bb[j].w, accq[i][j]);
                }
            }
        }

#pragma unroll
        for (int i = 0; i < 4; i++) {
            int r = ty + 16 * i;
            int qglob = qb * BQ + r;
#pragma unroll
            for (int j = 0; j < 4; j++) {
                int cidx = tx + 16 * j;
                int kglob = kb * BQ + cidx;
                Ss[r * SP + cidx] = (kglob <= qglob) ? accq[i][j] : -1e30f;
            }
        }
        __syncthreads();

#pragma unroll
        for (int i = 0; i < 8; i++) {
            int r = w * 8 + i;
            float s0 = Ss[r * SP + lane];
            float s1 = Ss[r * SP + lane + 32];
            float tmax = fmaxf(s0, s1);
#pragma unroll
            for (int off = 16; off; off >>= 1)
                tmax = fmaxf(tmax, __shfl_xor_sync(0xffffffffu, tmax, off));
            float mnew = fmaxf(m[i], tmax);
            float p0 = __expf(s0 - mnew);
            float p1 = __expf(s1 - mnew);
            Ss[r * SP + lane]      = p0;
            Ss[r * SP + lane + 32] = p1;
            float alpha = __expf(m[i] - mnew);
            float ps = p0 + p1;
#pragma unroll
            for (int off = 16; off; off >>= 1)
                ps += __shfl_xor_sync(0xffffffffu, ps, off);
            l[i] = l[i] * alpha + ps;
            m[i] = mnew;
            O[i][0] *= alpha; O[i][1] *= alpha;
            O[i][2] *= alpha; O[i][3] *= alpha;
        }
        __syncwarp();

        for (int k = 0; k < BQ; k++) {
            float4 v = *(float4*)&Vs[k * KP + lane * 4];
#pragma unroll
            for (int i = 0; i < 8; i++) {
                float p = Ss[(w * 8 + i) * SP + k];
                O[i][0] = fmaf(p, v.x, O[i][0]);
                O[i][1] = fmaf(p, v.y, O[i][1]);
                O[i][2] = fmaf(p, v.z, O[i][2]);
                O[i][3] = fmaf(p, v.w, O[i][3]);
            }
        }
    }

#pragma unroll
    for (int i = 0; i < 8; i++) {
        float inv = 1.0f / l[i];
        int r = w * 8 + i;
        float4 o;
        o.x = O[i][0] * inv; o.y = O[i][1] * inv;
        o.z = O[i][2] * inv; o.w = O[i][3] * inv;
        *(float4*)(Cc + (rowbase + r) * DMODEL + h * DHEAD + lane * 4) = o;
    }
}

// ---------------------------------------------------------------------------
extern "C" void kernel_launch(void* const* d_in, const int* in_sizes, int n_in,
                              void* d_out, int out_size)
{
    const float* x  = (const float*)d_in[0];
    const float* qw = (const float*)d_in[1];
    const float* kw = (const float*)d_in[2];
    const float* vw = (const float*)d_in[3];
    const float* ww = (const float*)d_in[4];
    const int* pos  = (const int*)d_in[5];
    float* out = (float*)d_out;

    float *Qb, *Kb, *Vb, *Cb;
    cudaGetSymbolAddress((void**)&Qb, g_Q);
    cudaGetSymbolAddress((void**)&Kb, g_K);
    cudaGetSymbolAddress((void**)&Vb, g_V);
    cudaGetSymbolAddress((void**)&Cb, g_C);

    __nv_bfloat16 *xhi, *xlo, *chi, *clo;
    __nv_bfloat16 *wqh, *wql, *wkh, *wkl, *wvh, *wvl, *woh, *wol;
    cudaGetSymbolAddress((void**)&xhi, g_xhi);
    cudaGetSymbolAddress((void**)&xlo, g_xlo);
    cudaGetSymbolAddress((void**)&chi, g_chi);
    cudaGetSymbolAddress((void**)&clo, g_clo);
    cudaGetSymbolAddress((void**)&wqh, g_wqhi);
    cudaGetSymbolAddress((void**)&wql, g_wqlo);
    cudaGetSymbolAddress((void**)&wkh, g_wkhi);
    cudaGetSymbolAddress((void**)&wkl, g_wklo);
    cudaGetSymbolAddress((void**)&wvh, g_wvhi);
    cudaGetSymbolAddress((void**)&wvl, g_wvlo);
    cudaGetSymbolAddress((void**)&woh, g_wohi);
    cudaGetSymbolAddress((void**)&wol, g_wolo);

    const int xn4 = MTOT * DMODEL / 4;
    const int wn4 = DMODEL * DMODEL / 4;
    split_kernel<<<(xn4 + 255) / 256, 256>>>(x,  xhi, xlo, xn4);
    split_kernel<<<(wn4 + 255) / 256, 256>>>(qw, wqh, wql, wn4);
    split_kernel<<<(wn4 + 255) / 256, 256>>>(kw, wkh, wkl, wn4);
    split_kernel<<<(wn4 + 255) / 256, 256>>>(vw, wvh, wvl, wn4);
    split_kernel<<<(wn4 + 255) / 256, 256>>>(ww, woh, wol, wn4);

    dim3 gg(DMODEL / 128, MTOT / 128);
    bf16x3_gemm<<<gg, 256>>>(xhi, xlo, wqh, wql, Qb, MTOT, DMODEL, DMODEL);
    bf16x3_gemm<<<gg, 256>>>(xhi, xlo, wkh, wkl, Kb, MTOT, DMODEL, DMODEL);
    bf16x3_gemm<<<gg, 256>>>(xhi, xlo, wvh, wvl, Vb, MTOT, DMODEL, DMODEL);

    int ropeN = 2 * BATCH * TSEQ * NHEAD * 64;
    rope_kernel<<<(ropeN + 255) / 256, 256>>>(Qb, Kb, pos);

    size_t asmem = (size_t)(3 * BQ * KP + BQ * SP) * sizeof(float);
    cudaFuncSetAttribute(attn_kernel,
                         cudaFuncAttributeMaxDynamicSharedMemorySize, (int)asmem);
    dim3 ga(TSEQ / BQ, BATCH * NHEAD);
    attn_kernel<<<ga, 256, asmem>>>(Qb, Kb, Vb, Cb);

    split_kernel<<<(xn4 + 255) / 256, 256>>>(Cb, chi, clo, xn4);
    bf16x3_gemm<<<gg, 256>>>(chi, clo, woh, wol, out, MTOT, DMODEL, DMODEL);
}

// round 10
// speedup vs baseline: 2.3852x; 1.0532x over previous
#include <cuda_runtime.h>
#include <cuda_bf16.h>
#include <mma.h>
#include <math.h>

#define BATCH 2
#define TSEQ 2048
#define DMODEL 2048
#define NHEAD 16
#define DHEAD 128
#define MTOT (BATCH*TSEQ)

// ---------------- scratch (__device__ globals; no allocs allowed) ----------
__device__ float g_Q[MTOT*DMODEL];
__device__ float g_K[MTOT*DMODEL];
__device__ float g_V[MTOT*DMODEL];

__device__ __nv_bfloat16 g_xhi[MTOT*DMODEL];
__device__ __nv_bfloat16 g_xlo[MTOT*DMODEL];
__device__ __nv_bfloat16 g_chi[MTOT*DMODEL];
__device__ __nv_bfloat16 g_clo[MTOT*DMODEL];
__device__ __nv_bfloat16 g_wqhi[DMODEL*DMODEL];
__device__ __nv_bfloat16 g_wqlo[DMODEL*DMODEL];
__device__ __nv_bfloat16 g_wkhi[DMODEL*DMODEL];
__device__ __nv_bfloat16 g_wklo[DMODEL*DMODEL];
__device__ __nv_bfloat16 g_wvhi[DMODEL*DMODEL];
__device__ __nv_bfloat16 g_wvlo[DMODEL*DMODEL];
__device__ __nv_bfloat16 g_wohi[DMODEL*DMODEL];
__device__ __nv_bfloat16 g_wolo[DMODEL*DMODEL];

// ---------------------------------------------------------------------------
// split fp32 -> bf16 hi + bf16 lo (residual)
// ---------------------------------------------------------------------------
__global__ void split_kernel(const float* __restrict__ in,
                             __nv_bfloat16* __restrict__ hi,
                             __nv_bfloat16* __restrict__ lo, int n4)
{
    int i = blockIdx.x * blockDim.x + threadIdx.x;
    if (i >= n4) return;
    float4 v = ((const float4*)in)[i];
    __nv_bfloat16 h0 = __float2bfloat16_rn(v.x);
    __nv_bfloat16 h1 = __float2bfloat16_rn(v.y);
    __nv_bfloat16 h2 = __float2bfloat16_rn(v.z);
    __nv_bfloat16 h3 = __float2bfloat16_rn(v.w);
    __nv_bfloat16 l0 = __float2bfloat16_rn(v.x - __bfloat162float(h0));
    __nv_bfloat16 l1 = __float2bfloat16_rn(v.y - __bfloat162float(h1));
    __nv_bfloat16 l2 = __float2bfloat16_rn(v.z - __bfloat162float(h2));
    __nv_bfloat16 l3 = __float2bfloat16_rn(v.w - __bfloat162float(h3));
    __nv_bfloat162 ha; ha.x = h0; ha.y = h1;
    __nv_bfloat162 hb; hb.x = h2; hb.y = h3;
    __nv_bfloat162 la; la.x = l0; la.y = l1;
    __nv_bfloat162 lb; lb.x = l2; lb.y = l3;
    ((__nv_bfloat162*)hi)[2*i]   = ha;
    ((__nv_bfloat162*)hi)[2*i+1] = hb;
    ((__nv_bfloat162*)lo)[2*i]   = la;
    ((__nv_bfloat162*)lo)[2*i+1] = lb;
}

// ---------------------------------------------------------------------------
// WMMA 3-term bf16 GEMM: C = Ah*Bh + Ah*Bl + Al*Bh (fp32 accum)  (unchanged)
// ---------------------------------------------------------------------------
#define LDA 40
#define LDB 136

__global__ __launch_bounds__(256) void bf16x3_gemm(
    const __nv_bfloat16* __restrict__ Ah, const __nv_bfloat16* __restrict__ Al,
    const __nv_bfloat16* __restrict__ Bh, const __nv_bfloat16* __restrict__ Bl,
    float* __restrict__ C, int M, int N, int K)
{
    __shared__ __nv_bfloat16 sAh[128*LDA];
    __shared__ __nv_bfloat16 sAl[128*LDA];
    __shared__ __nv_bfloat16 sBh[32*LDB];
    __shared__ __nv_bfloat16 sBl[32*LDB];

    const int tid  = threadIdx.x;
    const int warp = tid >> 5;
    const int wm   = warp >> 1;
    const int wn   = warp & 1;
    const int bx   = blockIdx.x, by = blockIdx.y;

    const __nv_bfloat16* gAh = Ah + (size_t)by * 128 * K;
    const __nv_bfloat16* gAl = Al + (size_t)by * 128 * K;
    const __nv_bfloat16* gBh = Bh + (size_t)bx * 128;
    const __nv_bfloat16* gBl = Bl + (size_t)bx * 128;

    const int c0 = tid, c1 = tid + 256;
    const int ar0 = c0 >> 2, ak0 = (c0 & 3) * 8;
    const int ar1 = c1 >> 2, ak1 = (c1 & 3) * 8;
    const int bk0 = c0 >> 4, bn0 = (c0 & 15) * 8;
    const int bk1 = c1 >> 4, bn1 = (c1 & 15) * 8;

    nvcuda::wmma::fragment<nvcuda::wmma::accumulator, 16, 16, 16, float> acc[2][4];
#pragma unroll
    for (int i = 0; i < 2; i++) {
#pragma unroll
        for (int j = 0; j < 4; j++) {
            nvcuda::wmma::fill_fragment(acc[i][j], 0.0f);
        }
    }

    *(float4*)&sAh[ar0*LDA + ak0] = *(const float4*)(gAh + (size_t)ar0 * K + ak0);
    *(float4*)&sAh[ar1*LDA + ak1] = *(const float4*)(gAh + (size_t)ar1 * K + ak1);
    *(float4*)&sAl[ar0*LDA + ak0] = *(const float4*)(gAl + (size_t)ar0 * K + ak0);
    *(float4*)&sAl[ar1*LDA + ak1] = *(const float4*)(gAl + (size_t)ar1 * K + ak1);
    *(float4*)&sBh[bk0*LDB + bn0] = *(const float4*)(gBh + (size_t)bk0 * N + bn0);
    *(float4*)&sBh[bk1*LDB + bn1] = *(const float4*)(gBh + (size_t)bk1 * N + bn1);
    *(float4*)&sBl[bk0*LDB + bn0] = *(const float4*)(gBl + (size_t)bk0 * N + bn0);
    *(float4*)&sBl[bk1*LDB + bn1] = *(const float4*)(gBl + (size_t)bk1 * N + bn1);
    __syncthreads();

    const int NK = K / 32;
    float4 pa0, pa1, pb0, pb1, qa0, qa1, qb0, qb1;

    for (int kt = 0; kt < NK; kt++) {
        const int k0 = (kt + 1) * 32;
        const bool more = (kt + 1 < NK);
        if (more) {
            pa0 = *(const float4*)(gAh + (size_t)ar0 * K + k0 + ak0);
            pa1 = *(const float4*)(gAh + (size_t)ar1 * K + k0 + ak1);
            qa0 = *(const float4*)(gAl + (size_t)ar0 * K + k0 + ak0);
            qa1 = *(const float4*)(gAl + (size_t)ar1 * K + k0 + ak1);
            pb0 = *(const float4*)(gBh + (size_t)(k0 + bk0) * N + bn0);
            pb1 = *(const float4*)(gBh + (size_t)(k0 + bk1) * N + bn1);
            qb0 = *(const float4*)(gBl + (size_t)(k0 + bk0) * N + bn0);
            qb1 = *(const float4*)(gBl + (size_t)(k0 + bk1) * N + bn1);
        }

#pragma unroll
        for (int ks = 0; ks < 2; ks++) {
            nvcuda::wmma::fragment<nvcuda::wmma::matrix_a, 16, 16, 16,
                                   __nv_bfloat16, nvcuda::wmma::row_major> aH[2], aL[2];
#pragma unroll
            for (int i = 0; i < 2; i++) {
                nvcuda::wmma::load_matrix_sync(aH[i],
                    &sAh[(wm*32 + i*16)*LDA + ks*16], LDA);
                nvcuda::wmma::load_matrix_sync(aL[i],
                    &sAl[(wm*32 + i*16)*LDA + ks*16], LDA);
            }
#pragma unroll
            for (int j = 0; j < 4; j++) {
                nvcuda::wmma::fragment<nvcuda::wmma::matrix_b, 16, 16, 16,
                                       __nv_bfloat16, nvcuda::wmma::row_major> bF;
                nvcuda::wmma::load_matrix_sync(bF,
                    &sBh[ks*16*LDB + wn*64 + j*16], LDB);
#pragma unroll
                for (int i = 0; i < 2; i++) {
                    nvcuda::wmma::mma_sync(acc[i][j], aH[i], bF, acc[i][j]);
                    nvcuda::wmma::mma_sync(acc[i][j], aL[i], bF, acc[i][j]);
                }
                nvcuda::wmma::load_matrix_sync(bF,
                    &sBl[ks*16*LDB + wn*64 + j*16], LDB);
#pragma unroll
                for (int i = 0; i < 2; i++) {
                    nvcuda::wmma::mma_sync(acc[i][j], aH[i], bF, acc[i][j]);
                }
            }
        }
        __syncthreads();

        if (more) {
            *(float4*)&sAh[ar0*LDA + ak0] = pa0;
            *(float4*)&sAh[ar1*LDA + ak1] = pa1;
            *(float4*)&sAl[ar0*LDA + ak0] = qa0;
            *(float4*)&sAl[ar1*LDA + ak1] = qa1;
            *(float4*)&sBh[bk0*LDB + bn0] = pb0;
            *(float4*)&sBh[bk1*LDB + bn1] = pb1;
            *(float4*)&sBl[bk0*LDB + bn0] = qb0;
            *(float4*)&sBl[bk1*LDB + bn1] = qb1;
            __syncthreads();
        }
    }

    float* Cb = C + (size_t)(by * 128) * N + bx * 128;
#pragma unroll
    for (int i = 0; i < 2; i++) {
#pragma unroll
        for (int j = 0; j < 4; j++) {
            nvcuda::wmma::store_matrix_sync(
                Cb + (size_t)(wm*32 + i*16) * N + wn*64 + j*16,
                acc[i][j], N, nvcuda::wmma::mem_row_major);
        }
    }
}

// ---------------------------------------------------------------------------
// RoPE (in place on Q and K)
// ---------------------------------------------------------------------------
__global__ void rope_kernel(float* __restrict__ Q, float* __restrict__ K,
                            const int* __restrict__ posp)
{
    const int total = BATCH * TSEQ * NHEAD * 64;
    int idx = blockIdx.x * blockDim.x + threadIdx.x;
    if (idx >= 2 * total) return;
    float* buf = (idx < total) ? Q : K;
    int e = (idx < total) ? idx : idx - total;
    int j = e & 63;
    int h = (e >> 6) & (NHEAD - 1);
    int t = (e >> 10) & (TSEQ - 1);
    int b = e >> 21;
    int p0 = *posp; if (p0 < 0) p0 = 0;
    float inv = __expf(-0.14391156463f * (float)j);
    float ang = (float)(p0 + t) * inv;
    float s, c;
    sincosf(ang, &s, &c);
    size_t base = ((size_t)(b * TSEQ + t)) * DMODEL + h * DHEAD + j;
    float x1 = buf[base], x2 = buf[base + 64];
    buf[base]      = x1 * c - x2 * s;
    buf[base + 64] = x1 * s + x2 * c;
}

// ---------------------------------------------------------------------------
// Flash attention on tensor cores, 3-term bf16 split for S=QK^T and P*V.
// Block = 64 queries x one (b,h). 256 threads = 8 warps (4m x 2n).
// Epilogue writes ctx directly as bf16 hi/lo for the output projection.
// ---------------------------------------------------------------------------
#define SPF 136   // fp32 row stride (Ss / Ot)
#define LDQ 136   // bf16 row stride (Q/K/V tiles)
#define LDP 72    // bf16 row stride (P tiles)

// smem byte offsets (all 16B aligned)
#define OFF_SS   0
#define OFF_QH   (64*SPF*4)                 // 34816
#define OFF_QL   (OFF_QH + 64*LDQ*2)
#define OFF_KH   (OFF_QL + 64*LDQ*2)
#define OFF_KL   (OFF_KH + 64*LDQ*2)
#define OFF_VH   (OFF_KL + 64*LDQ*2)
#define OFF_VL   (OFF_VH + 64*LDQ*2)
#define OFF_PH   (OFF_VL + 64*LDQ*2)
#define OFF_PL   (OFF_PH + 64*LDP*2)
#define OFF_AL   (OFF_PL + 64*LDP*2)
#define OFF_LL   (OFF_AL + 64*4)
#define ATT_SMEM (OFF_LL + 64*4)

__device__ __forceinline__ void split4s(float4 v, float sc,
                                        __nv_bfloat16* hp, __nv_bfloat16* lp)
{
    v.x *= sc; v.y *= sc; v.z *= sc; v.w *= sc;
    __nv_bfloat16 h0 = __float2bfloat16_rn(v.x);
    __nv_bfloat16 h1 = __float2bfloat16_rn(v.y);
    __nv_bfloat16 h2 = __float2bfloat16_rn(v.z);
    __nv_bfloat16 h3 = __float2bfloat16_rn(v.w);
    __nv_bfloat16 l0 = __float2bfloat16_rn(v.x - __bfloat162float(h0));
    __nv_bfloat16 l1 = __float2bfloat16_rn(v.y - __bfloat162float(h1));
    __nv_bfloat16 l2 = __float2bfloat16_rn(v.z - __bfloat162float(h2));
    __nv_bfloat16 l3 = __float2bfloat16_rn(v.w - __bfloat162float(h3));
    __nv_bfloat162 a; a.x = h0; a.y = h1;
    __nv_bfloat162 b; b.x = h2; b.y = h3;
    __nv_bfloat162 c; c.x = l0; c.y = l1;
    __nv_bfloat162 d; d.x = l2; d.y = l3;
    *(__nv_bfloat162*)(hp)     = a;
    *(__nv_bfloat162*)(hp + 2) = b;
    *(__nv_bfloat162*)(lp)     = c;
    *(__nv_bfloat162*)(lp + 2) = d;
}

__global__ __launch_bounds__(256) void attn_mma_kernel(
    const float* __restrict__ Q, const float* __restrict__ Kt,
    const float* __restrict__ V,
    __nv_bfloat16* __restrict__ Chi, __nv_bfloat16* __restrict__ Clo)
{
    extern __shared__ char smc[];
    float*         Ss = (float*)(smc + OFF_SS);
    __nv_bfloat16* Qh = (__nv_bfloat16*)(smc + OFF_QH);
    __nv_bfloat16* Ql = (__nv_bfloat16*)(smc + OFF_QL);
    __nv_bfloat16* Kh = (__nv_bfloat16*)(smc + OFF_KH);
    __nv_bfloat16* Kl = (__nv_bfloat16*)(smc + OFF_KL);
    __nv_bfloat16* Vh = (__nv_bfloat16*)(smc + OFF_VH);
    __nv_bfloat16* Vl = (__nv_bfloat16*)(smc + OFF_VL);
    __nv_bfloat16* Ph = (__nv_bfloat16*)(smc + OFF_PH);
    __nv_bfloat16* Pl = (__nv_bfloat16*)(smc + OFF_PL);
    float*     salpha = (float*)(smc + OFF_AL);
    float*         sl = (float*)(smc + OFF_LL);

    const int tid  = threadIdx.x;
    const int lane = tid & 31, w = tid >> 5;
    const int wm   = w >> 1, wn = w & 1;
    const int qb   = gridDim.x - 1 - blockIdx.x;   // big tiles first
    const int bh   = blockIdx.y;
    const int b    = bh >> 4, h = bh & (NHEAD - 1);
    const float scale = 0.08838834764831845f;      // 1/sqrt(128)
    const size_t rowbase = (size_t)b * TSEQ + (size_t)qb * 64;

    // per-thread O ownership: row r, cols c0..c0+31
    const int orow = tid >> 2;
    const int ocol = (tid & 3) * 32;
    float O[32];
#pragma unroll
    for (int i = 0; i < 32; i++) O[i] = 0.f;

    // softmax state (warp w owns rows w*8..w*8+7)
    float m[8], l[8];
#pragma unroll
    for (int i = 0; i < 8; i++) { m[i] = -1e30f; l[i] = 0.f; }

    // load + split Q (pre-scaled)
    for (int i = tid; i < 64 * 32; i += 256) {
        int r = i >> 5, c4 = (i & 31) * 4;
        float4 q = *(const float4*)(Q + (rowbase + r) * DMODEL + h * DHEAD + c4);
        split4s(q, scale, &Qh[r * LDQ + c4], &Ql[r * LDQ + c4]);
    }

    for (int kb = 0; kb <= qb; kb++) {
        __syncthreads();  // prev iter fully consumed (also orders Q on iter 0)

        // load + split K, V tiles
        size_t kbase = (size_t)b * TSEQ + (size_t)kb * 64;
        for (int i = tid; i < 64 * 32; i += 256) {
            int r = i >> 5, c4 = (i & 31) * 4;
            float4 kv = *(const float4*)(Kt + (kbase + r) * DMODEL + h * DHEAD + c4);
            split4s(kv, 1.0f, &Kh[r * LDQ + c4], &Kl[r * LDQ + c4]);
            float4 vv = *(const float4*)(V + (kbase + r) * DMODEL + h * DHEAD + c4);
            split4s(vv, 1.0f, &Vh[r * LDQ + c4], &Vl[r * LDQ + c4]);
        }
        __syncthreads();

        // ---- S = Q K^T (warp tile 16 x 32) ----
        {
            nvcuda::wmma::fragment<nvcuda::wmma::accumulator, 16, 16, 16, float> sacc[2];
#pragma unroll
            for (int j = 0; j < 2; j++) nvcuda::wmma::fill_fragment(sacc[j], 0.0f);
#pragma unroll
            for (int k8 = 0; k8 < 8; k8++) {
                nvcuda::wmma::fragment<nvcuda::wmma::matrix_a, 16, 16, 16,
                    __nv_bfloat16, nvcuda::wmma::row_major> aH, aL;
                nvcuda::wmma::load_matrix_sync(aH, &Qh[(wm*16)*LDQ + k8*16], LDQ);
                nvcuda::wmma::load_matrix_sync(aL, &Ql[(wm*16)*LDQ + k8*16], LDQ);
#pragma unroll
                for (int j = 0; j < 2; j++) {
                    nvcuda::wmma::fragment<nvcuda::wmma::matrix_b, 16, 16, 16,
                        __nv_bfloat16, nvcuda::wmma::col_major> bF;
                    nvcuda::wmma::load_matrix_sync(bF,
                        &Kh[(wn*32 + j*16)*LDQ + k8*16], LDQ);
                    nvcuda::wmma::mma_sync(sacc[j], aH, bF, sacc[j]);
                    nvcuda::wmma::mma_sync(sacc[j], aL, bF, sacc[j]);
                    nvcuda::wmma::load_matrix_sync(bF,
                        &Kl[(wn*32 + j*16)*LDQ + k8*16], LDQ);
                    nvcuda::wmma::mma_sync(sacc[j], aH, bF, sacc[j]);
                }
            }
#pragma unroll
            for (int j = 0; j < 2; j++) {
                nvcuda::wmma::store_matrix_sync(
                    &Ss[(wm*16)*SPF + wn*32 + j*16], sacc[j], SPF,
                    nvcuda::wmma::mem_row_major);
            }
        }
        __syncthreads();

        // ---- online softmax (warp w: rows w*8..w*8+7) ----
#pragma unroll
        for (int i = 0; i < 8; i++) {
            int r = w * 8 + i;
            int qglob = qb * 64 + r;
            int kg0 = kb * 64 + lane;
            int kg1 = kg0 + 32;
            float s0 = (kg0 <= qglob) ? Ss[r * SPF + lane]      : -1e30f;
            float s1 = (kg1 <= qglob) ? Ss[r * SPF + lane + 32] : -1e30f;
            float tmax = fmaxf(s0, s1);
#pragma unroll
            for (int off = 16; off; off >>= 1)
                tmax = fmaxf(tmax, __shfl_xor_sync(0xffffffffu, tmax, off));
            float mnew = fmaxf(m[i], tmax);
            float p0 = __expf(s0 - mnew);
            float p1 = __expf(s1 - mnew);
            float alpha = __expf(m[i] - mnew);
            float ps = p0 + p1;
#pragma unroll
            for (int off = 16; off; off >>= 1)
                ps += __shfl_xor_sync(0xffffffffu, ps, off);
            l[i] = l[i] * alpha + ps;
            m[i] = mnew;
            __nv_bfloat16 h0 = __float2bfloat16_rn(p0);
            __nv_bfloat16 h1 = __float2bfloat16_rn(p1);
            Ph[r * LDP + lane]      = h0;
            Ph[r * LDP + lane + 32] = h1;
            Pl[r * LDP + lane]      = __float2bfloat16_rn(p0 - __bfloat162float(h0));
            Pl[r * LDP + lane + 32] = __float2bfloat16_rn(p1 - __bfloat162float(h1));
            if (lane == 0) salpha[r] = alpha;
        }
        __syncthreads();

        // ---- Ot = P V (warp tile 16 x 64) ----
        {
            nvcuda::wmma::fragment<nvcuda::wmma::accumulator, 16, 16, 16, float> oacc[4];
#pragma unroll
            for (int j = 0; j < 4; j++) nvcuda::wmma::fill_fragment(oacc[j], 0.0f);
#pragma unroll
            for (int k4 = 0; k4 < 4; k4++) {
                nvcuda::wmma::fragment<nvcuda::wmma::matrix_a, 16, 16, 16,
                    __nv_bfloat16, nvcuda::wmma::row_major> aH, aL;
                nvcuda::wmma::load_matrix_sync(aH, &Ph[(wm*16)*LDP + k4*16], LDP);
                nvcuda::wmma::load_matrix_sync(aL, &Pl[(wm*16)*LDP + k4*16], LDP);
#pragma unroll
                for (int j = 0; j < 4; j++) {
                    nvcuda::wmma::fragment<nvcuda::wmma::matrix_b, 16, 16, 16,
                        __nv_bfloat16, nvcuda::wmma::row_major> bF;
                    nvcuda::wmma::load_matrix_sync(bF,
                        &Vh[(k4*16)*LDQ + wn*64 + j*16], LDQ);
                    nvcuda::wmma::mma_sync(oacc[j], aH, bF, oacc[j]);
                    nvcuda::wmma::mma_sync(oacc[j], aL, bF, oacc[j]);
                    nvcuda::wmma::load_matrix_sync(bF,
                        &Vl[(k4*16)*LDQ + wn*64 + j*16], LDQ);
                    nvcuda::wmma::mma_sync(oacc[j], aH, bF, oacc[j]);
                }
            }
#pragma unroll
            for (int j = 0; j < 4; j++) {
                nvcuda::wmma::store_matrix_sync(
                    &Ss[(wm*16)*SPF + wn*64 + j*16], oacc[j], SPF,
                    nvcuda::wmma::mem_row_major);
            }
        }
        __syncthreads();

        // ---- O = O*alpha + Ot (per-thread, no fragment-layout assumptions) ----
        {
            float a = salpha[orow];
#pragma unroll
            for (int j8 = 0; j8 < 8; j8++) {
                float4 t = *(float4*)&Ss[orow * SPF + ocol + j8 * 4];
                O[j8*4+0] = O[j8*4+0] * a + t.x;
                O[j8*4+1] = O[j8*4+1] * a + t.y;
                O[j8*4+2] = O[j8*4+2] * a + t.z;
                O[j8*4+3] = O[j8*4+3] * a + t.w;
            }
        }
    }

    // publish 1/l per row
    if (lane == 0) {
#pragma unroll
        for (int i = 0; i < 8; i++) sl[w * 8 + i] = 1.0f / l[i];
    }
    __syncthreads();

    // epilogue: normalize + bf16 hi/lo split directly (ctx layout [b,t,d])
    {
        float inv = sl[orow];
        size_t gbase = (rowbase + orow) * DMODEL + h * DHEAD + ocol;
#pragma unroll
        for (int j = 0; j < 16; j++) {
            float v0 = O[2*j]   * inv;
            float v1 = O[2*j+1] * inv;
            __nv_bfloat16 h0 = __float2bfloat16_rn(v0);
            __nv_bfloat16 h1 = __float2bfloat16_rn(v1);
            __nv_bfloat162 hp; hp.x = h0; hp.y = h1;
            __nv_bfloat162 lp;
            lp.x = __float2bfloat16_rn(v0 - __bfloat162float(h0));
            lp.y = __float2bfloat16_rn(v1 - __bfloat162float(h1));
            *(__nv_bfloat162*)(Chi + gbase + 2*j) = hp;
            *(__nv_bfloat162*)(Clo + gbase + 2*j) = lp;
        }
    }
}

// ---------------------------------------------------------------------------
extern "C" void kernel_launch(void* const* d_in, const int* in_sizes, int n_in,
                              void* d_out, int out_size)
{
    const float* x  = (const float*)d_in[0];
    const float* qw = (const float*)d_in[1];
    const float* kw = (const float*)d_in[2];
    const float* vw = (const float*)d_in[3];
    const float* ww = (const float*)d_in[4];
    const int* pos  = (const int*)d_in[5];
    float* out = (float*)d_out;

    float *Qb, *Kb, *Vb;
    cudaGetSymbolAddress((void**)&Qb, g_Q);
    cudaGetSymbolAddress((void**)&Kb, g_K);
    cudaGetSymbolAddress((void**)&Vb, g_V);

    __nv_bfloat16 *xhi, *xlo, *chi, *clo;
    __nv_bfloat16 *wqh, *wql, *wkh, *wkl, *wvh, *wvl, *woh, *wol;
    cudaGetSymbolAddress((void**)&xhi, g_xhi);
    cudaGetSymbolAddress((void**)&xlo, g_xlo);
    cudaGetSymbolAddress((void**)&chi, g_chi);
    cudaGetSymbolAddress((void**)&clo, g_clo);
    cudaGetSymbolAddress((void**)&wqh, g_wqhi);
    cudaGetSymbolAddress((void**)&wql, g_wqlo);
    cudaGetSymbolAddress((void**)&wkh, g_wkhi);
    cudaGetSymbolAddress((void**)&wkl, g_wklo);
    cudaGetSymbolAddress((void**)&wvh, g_wvhi);
    cudaGetSymbolAddress((void**)&wvl, g_wvlo);
    cudaGetSymbolAddress((void**)&woh, g_wohi);
    cudaGetSymbolAddress((void**)&wol, g_wolo);

    const int xn4 = MTOT * DMODEL / 4;
    const int wn4 = DMODEL * DMODEL / 4;
    split_kernel<<<(xn4 + 255) / 256, 256>>>(x,  xhi, xlo, xn4);
    split_kernel<<<(wn4 + 255) / 256, 256>>>(qw, wqh, wql, wn4);
    split_kernel<<<(wn4 + 255) / 256, 256>>>(kw, wkh, wkl, wn4);
    split_kernel<<<(wn4 + 255) / 256, 256>>>(vw, wvh, wvl, wn4);
    split_kernel<<<(wn4 + 255) / 256, 256>>>(ww, woh, wol, wn4);

    dim3 gg(DMODEL / 128, MTOT / 128);
    bf16x3_gemm<<<gg, 256>>>(xhi, xlo, wqh, wql, Qb, MTOT, DMODEL, DMODEL);
    bf16x3_gemm<<<gg, 256>>>(xhi, xlo, wkh, wkl, Kb, MTOT, DMODEL, DMODEL);
    bf16x3_gemm<<<gg, 256>>>(xhi, xlo, wvh, wvl, Vb, MTOT, DMODEL, DMODEL);

    int ropeN = 2 * BATCH * TSEQ * NHEAD * 64;
    rope_kernel<<<(ropeN + 255) / 256, 256>>>(Qb, Kb, pos);

    cudaFuncSetAttribute(attn_mma_kernel,
                         cudaFuncAttributeMaxDynamicSharedMemorySize, ATT_SMEM);
    dim3 ga(TSEQ / 64, BATCH * NHEAD);
    attn_mma_kernel<<<ga, 256, ATT_SMEM>>>(Qb, Kb, Vb, chi, clo);

    bf16x3_gemm<<<gg, 256>>>(chi, clo, woh, wol, out, MTOT, DMODEL, DMODEL);
}

// round 11
// speedup vs baseline: 2.5146x; 1.0542x over previous
#include <cuda_runtime.h>
#include <cuda_bf16.h>
#include <mma.h>
#include <math.h>

#define BATCH 2
#define TSEQ 2048
#define DMODEL 2048
#define NHEAD 16
#define DHEAD 128
#define MTOT (BATCH*TSEQ)

// ---------------- scratch (__device__ globals; no allocs allowed) ----------
__device__ float g_Q[MTOT*DMODEL];
__device__ float g_K[MTOT*DMODEL];
__device__ float g_V[MTOT*DMODEL];

__device__ __nv_bfloat16 g_xhi[MTOT*DMODEL];
__device__ __nv_bfloat16 g_xlo[MTOT*DMODEL];
__device__ __nv_bfloat16 g_chi[MTOT*DMODEL];
__device__ __nv_bfloat16 g_clo[MTOT*DMODEL];
__device__ __nv_bfloat16 g_qh[MTOT*DMODEL];
__device__ __nv_bfloat16 g_ql[MTOT*DMODEL];
__device__ __nv_bfloat16 g_kh[MTOT*DMODEL];
__device__ __nv_bfloat16 g_kl[MTOT*DMODEL];
__device__ __nv_bfloat16 g_vh[MTOT*DMODEL];
__device__ __nv_bfloat16 g_vl[MTOT*DMODEL];
__device__ __nv_bfloat16 g_wqhi[DMODEL*DMODEL];
__device__ __nv_bfloat16 g_wqlo[DMODEL*DMODEL];
__device__ __nv_bfloat16 g_wkhi[DMODEL*DMODEL];
__device__ __nv_bfloat16 g_wklo[DMODEL*DMODEL];
__device__ __nv_bfloat16 g_wvhi[DMODEL*DMODEL];
__device__ __nv_bfloat16 g_wvlo[DMODEL*DMODEL];
__device__ __nv_bfloat16 g_wohi[DMODEL*DMODEL];
__device__ __nv_bfloat16 g_wolo[DMODEL*DMODEL];

// ---------------------------------------------------------------------------
// split fp32 -> bf16 hi + bf16 lo (residual)
// ---------------------------------------------------------------------------
__global__ void split_kernel(const float* __restrict__ in,
                             __nv_bfloat16* __restrict__ hi,
                             __nv_bfloat16* __restrict__ lo, int n4)
{
    int i = blockIdx.x * blockDim.x + threadIdx.x;
    if (i >= n4) return;
    float4 v = ((const float4*)in)[i];
    __nv_bfloat16 h0 = __float2bfloat16_rn(v.x);
    __nv_bfloat16 h1 = __float2bfloat16_rn(v.y);
    __nv_bfloat16 h2 = __float2bfloat16_rn(v.z);
    __nv_bfloat16 h3 = __float2bfloat16_rn(v.w);
    __nv_bfloat16 l0 = __float2bfloat16_rn(v.x - __bfloat162float(h0));
    __nv_bfloat16 l1 = __float2bfloat16_rn(v.y - __bfloat162float(h1));
    __nv_bfloat16 l2 = __float2bfloat16_rn(v.z - __bfloat162float(h2));
    __nv_bfloat16 l3 = __float2bfloat16_rn(v.w - __bfloat162float(h3));
    __nv_bfloat162 ha; ha.x = h0; ha.y = h1;
    __nv_bfloat162 hb; hb.x = h2; hb.y = h3;
    __nv_bfloat162 la; la.x = l0; la.y = l1;
    __nv_bfloat162 lb; lb.x = l2; lb.y = l3;
    ((__nv_bfloat162*)hi)[2*i]   = ha;
    ((__nv_bfloat162*)hi)[2*i+1] = hb;
    ((__nv_bfloat162*)lo)[2*i]   = la;
    ((__nv_bfloat162*)lo)[2*i+1] = lb;
}

// ---------------------------------------------------------------------------
// fused RoPE + bf16 split for Q (pre-scaled by 1/sqrt(dh)) and K
// ---------------------------------------------------------------------------
__global__ void rope_split_kernel(const float* __restrict__ Q,
                                  const float* __restrict__ K,
                                  __nv_bfloat16* __restrict__ Qh,
                                  __nv_bfloat16* __restrict__ Ql,
                                  __nv_bfloat16* __restrict__ Kh,
                                  __nv_bfloat16* __restrict__ Kl,
                                  const int* __restrict__ posp)
{
    const int total = BATCH * TSEQ * NHEAD * 64;
    int idx = blockIdx.x * blockDim.x + threadIdx.x;
    if (idx >= 2 * total) return;
    const bool isq = (idx < total);
    int e = isq ? idx : idx - total;
    int j = e & 63;
    int h = (e >> 6) & (NHEAD - 1);
    int t = (e >> 10) & (TSEQ - 1);
    int b = e >> 21;
    int p0 = *posp; if (p0 < 0) p0 = 0;
    float inv = __expf(-0.14391156463f * (float)j);   // 10000^(-j/64)
    float ang = (float)(p0 + t) * inv;
    float s, c;
    sincosf(ang, &s, &c);
    size_t base = ((size_t)(b * TSEQ + t)) * DMODEL + h * DHEAD + j;
    const float* src = isq ? Q : K;
    float x1 = src[base], x2 = src[base + 64];
    float y1 = x1 * c - x2 * s;
    float y2 = x1 * s + x2 * c;
    if (isq) {
        const float sc = 0.08838834764831845f;        // 1/sqrt(128)
        y1 *= sc; y2 *= sc;
    }
    __nv_bfloat16* hi = isq ? Qh : Kh;
    __nv_bfloat16* lo = isq ? Ql : Kl;
    __nv_bfloat16 h1 = __float2bfloat16_rn(y1);
    __nv_bfloat16 h2 = __float2bfloat16_rn(y2);
    hi[base]      = h1;
    hi[base + 64] = h2;
    lo[base]      = __float2bfloat16_rn(y1 - __bfloat162float(h1));
    lo[base + 64] = __float2bfloat16_rn(y2 - __bfloat162float(h2));
}

// ---------------------------------------------------------------------------
// WMMA 3-term bf16 GEMM: C = Ah*Bh + Ah*Bl + Al*Bh (fp32 accum)  (unchanged)
// ---------------------------------------------------------------------------
#define LDA 40
#define LDB 136

__global__ __launch_bounds__(256) void bf16x3_gemm(
    const __nv_bfloat16* __restrict__ Ah, const __nv_bfloat16* __restrict__ Al,
    const __nv_bfloat16* __restrict__ Bh, const __nv_bfloat16* __restrict__ Bl,
    float* __restrict__ C, int M, int N, int K)
{
    __shared__ __nv_bfloat16 sAh[128*LDA];
    __shared__ __nv_bfloat16 sAl[128*LDA];
    __shared__ __nv_bfloat16 sBh[32*LDB];
    __shared__ __nv_bfloat16 sBl[32*LDB];

    const int tid  = threadIdx.x;
    const int warp = tid >> 5;
    const int wm   = warp >> 1;
    const int wn   = warp & 1;
    const int bx   = blockIdx.x, by = blockIdx.y;

    const __nv_bfloat16* gAh = Ah + (size_t)by * 128 * K;
    const __nv_bfloat16* gAl = Al + (size_t)by * 128 * K;
    const __nv_bfloat16* gBh = Bh + (size_t)bx * 128;
    const __nv_bfloat16* gBl = Bl + (size_t)bx * 128;

    const int c0 = tid, c1 = tid + 256;
    const int ar0 = c0 >> 2, ak0 = (c0 & 3) * 8;
    const int ar1 = c1 >> 2, ak1 = (c1 & 3) * 8;
    const int bk0 = c0 >> 4, bn0 = (c0 & 15) * 8;
    const int bk1 = c1 >> 4, bn1 = (c1 & 15) * 8;

    nvcuda::wmma::fragment<nvcuda::wmma::accumulator, 16, 16, 16, float> acc[2][4];
#pragma unroll
    for (int i = 0; i < 2; i++) {
#pragma unroll
        for (int j = 0; j < 4; j++) {
            nvcuda::wmma::fill_fragment(acc[i][j], 0.0f);
        }
    }

    *(float4*)&sAh[ar0*LDA + ak0] = *(const float4*)(gAh + (size_t)ar0 * K + ak0);
    *(float4*)&sAh[ar1*LDA + ak1] = *(const float4*)(gAh + (size_t)ar1 * K + ak1);
    *(float4*)&sAl[ar0*LDA + ak0] = *(const float4*)(gAl + (size_t)ar0 * K + ak0);
    *(float4*)&sAl[ar1*LDA + ak1] = *(const float4*)(gAl + (size_t)ar1 * K + ak1);
    *(float4*)&sBh[bk0*LDB + bn0] = *(const float4*)(gBh + (size_t)bk0 * N + bn0);
    *(float4*)&sBh[bk1*LDB + bn1] = *(const float4*)(gBh + (size_t)bk1 * N + bn1);
    *(float4*)&sBl[bk0*LDB + bn0] = *(const float4*)(gBl + (size_t)bk0 * N + bn0);
    *(float4*)&sBl[bk1*LDB + bn1] = *(const float4*)(gBl + (size_t)bk1 * N + bn1);
    __syncthreads();

    const int NK = K / 32;
    float4 pa0, pa1, pb0, pb1, qa0, qa1, qb0, qb1;

    for (int kt = 0; kt < NK; kt++) {
        const int k0 = (kt + 1) * 32;
        const bool more = (kt + 1 < NK);
        if (more) {
            pa0 = *(const float4*)(gAh + (size_t)ar0 * K + k0 + ak0);
            pa1 = *(const float4*)(gAh + (size_t)ar1 * K + k0 + ak1);
            qa0 = *(const float4*)(gAl + (size_t)ar0 * K + k0 + ak0);
            qa1 = *(const float4*)(gAl + (size_t)ar1 * K + k0 + ak1);
            pb0 = *(const float4*)(gBh + (size_t)(k0 + bk0) * N + bn0);
            pb1 = *(const float4*)(gBh + (size_t)(k0 + bk1) * N + bn1);
            qb0 = *(const float4*)(gBl + (size_t)(k0 + bk0) * N + bn0);
            qb1 = *(const float4*)(gBl + (size_t)(k0 + bk1) * N + bn1);
        }

#pragma unroll
        for (int ks = 0; ks < 2; ks++) {
            nvcuda::wmma::fragment<nvcuda::wmma::matrix_a, 16, 16, 16,
                                   __nv_bfloat16, nvcuda::wmma::row_major> aH[2], aL[2];
#pragma unroll
            for (int i = 0; i < 2; i++) {
                nvcuda::wmma::load_matrix_sync(aH[i],
                    &sAh[(wm*32 + i*16)*LDA + ks*16], LDA);
                nvcuda::wmma::load_matrix_sync(aL[i],
                    &sAl[(wm*32 + i*16)*LDA + ks*16], LDA);
            }
#pragma unroll
            for (int j = 0; j < 4; j++) {
                nvcuda::wmma::fragment<nvcuda::wmma::matrix_b, 16, 16, 16,
                                       __nv_bfloat16, nvcuda::wmma::row_major> bF;
                nvcuda::wmma::load_matrix_sync(bF,
                    &sBh[ks*16*LDB + wn*64 + j*16], LDB);
#pragma unroll
                for (int i = 0; i < 2; i++) {
                    nvcuda::wmma::mma_sync(acc[i][j], aH[i], bF, acc[i][j]);
                    nvcuda::wmma::mma_sync(acc[i][j], aL[i], bF, acc[i][j]);
                }
                nvcuda::wmma::load_matrix_sync(bF,
                    &sBl[ks*16*LDB + wn*64 + j*16], LDB);
#pragma unroll
                for (int i = 0; i < 2; i++) {
                    nvcuda::wmma::mma_sync(acc[i][j], aH[i], bF, acc[i][j]);
                }
            }
        }
        __syncthreads();

        if (more) {
            *(float4*)&sAh[ar0*LDA + ak0] = pa0;
            *(float4*)&sAh[ar1*LDA + ak1] = pa1;
            *(float4*)&sAl[ar0*LDA + ak0] = qa0;
            *(float4*)&sAl[ar1*LDA + ak1] = qa1;
            *(float4*)&sBh[bk0*LDB + bn0] = pb0;
            *(float4*)&sBh[bk1*LDB + bn1] = pb1;
            *(float4*)&sBl[bk0*LDB + bn0] = qb0;
            *(float4*)&sBl[bk1*LDB + bn1] = qb1;
            __syncthreads();
        }
    }

    float* Cb = C + (size_t)(by * 128) * N + bx * 128;
#pragma unroll
    for (int i = 0; i < 2; i++) {
#pragma unroll
        for (int j = 0; j < 4; j++) {
            nvcuda::wmma::store_matrix_sync(
                Cb + (size_t)(wm*32 + i*16) * N + wn*64 + j*16,
                acc[i][j], N, nvcuda::wmma::mem_row_major);
        }
    }
}

// ---------------------------------------------------------------------------
// Flash attention, tensor cores, pre-split bf16 inputs. 512 thr = 16 warps.
// Block = 64 queries x one (b,h).
// ---------------------------------------------------------------------------
#define SPF 136   // fp32 row stride (Ss)
#define LDQ 136   // bf16 row stride (Q/K/V tiles)
#define LDP 72    // bf16 row stride (P tiles)

#define OFF_SS   0
#define OFF_QH   (64*SPF*4)
#define OFF_QL   (OFF_QH + 64*LDQ*2)
#define OFF_KH   (OFF_QL + 64*LDQ*2)
#define OFF_KL   (OFF_KH + 64*LDQ*2)
#define OFF_VH   (OFF_KL + 64*LDQ*2)
#define OFF_VL   (OFF_VH + 64*LDQ*2)
#define OFF_PH   (OFF_VL + 64*LDQ*2)
#define OFF_PL   (OFF_PH + 64*LDP*2)
#define OFF_AL   (OFF_PL + 64*LDP*2)
#define OFF_LL   (OFF_AL + 64*4)
#define ATT_SMEM (OFF_LL + 64*4)

__global__ __launch_bounds__(512) void attn_mma_kernel(
    const __nv_bfloat16* __restrict__ Qh_g, const __nv_bfloat16* __restrict__ Ql_g,
    const __nv_bfloat16* __restrict__ Kh_g, const __nv_bfloat16* __restrict__ Kl_g,
    const __nv_bfloat16* __restrict__ Vh_g, const __nv_bfloat16* __restrict__ Vl_g,
    __nv_bfloat16* __restrict__ Chi, __nv_bfloat16* __restrict__ Clo)
{
    extern __shared__ char smc[];
    float*         Ss = (float*)(smc + OFF_SS);
    __nv_bfloat16* Qh = (__nv_bfloat16*)(smc + OFF_QH);
    __nv_bfloat16* Ql = (__nv_bfloat16*)(smc + OFF_QL);
    __nv_bfloat16* Kh = (__nv_bfloat16*)(smc + OFF_KH);
    __nv_bfloat16* Kl = (__nv_bfloat16*)(smc + OFF_KL);
    __nv_bfloat16* Vh = (__nv_bfloat16*)(smc + OFF_VH);
    __nv_bfloat16* Vl = (__nv_bfloat16*)(smc + OFF_VL);
    __nv_bfloat16* Ph = (__nv_bfloat16*)(smc + OFF_PH);
    __nv_bfloat16* Pl = (__nv_bfloat16*)(smc + OFF_PL);
    float*     salpha = (float*)(smc + OFF_AL);
    float*         sl = (float*)(smc + OFF_LL);

    const int tid  = threadIdx.x;
    const int lane = tid & 31, w = tid >> 5;       // 16 warps
    const int wm   = w >> 2, wn = w & 3;           // 4 x 4
    const int qb   = gridDim.x - 1 - blockIdx.x;   // big tiles first
    const int bh   = blockIdx.y;
    const int b    = bh >> 4, h = bh & (NHEAD - 1);
    const size_t rowbase = (size_t)b * TSEQ + (size_t)qb * 64;

    // per-thread O ownership: row orow, 16 cols from ocol
    const int orow = tid >> 3;
    const int ocol = (tid & 7) * 16;
    float O[16];
#pragma unroll
    for (int i = 0; i < 16; i++) O[i] = 0.f;

    // softmax state: warp w owns rows w*4..w*4+3
    float m[4], l[4];
#pragma unroll
    for (int i = 0; i < 4; i++) { m[i] = -1e30f; l[i] = 0.f; }

    // load pre-split Q (1024 chunks of 8 bf16 per tile; 2 tiles)
    for (int i = tid; i < 64 * 16; i += 512) {
        int r = i >> 4, c8 = (i & 15) * 8;
        *(float4*)&Qh[r * LDQ + c8] =
            *(const float4*)(Qh_g + (rowbase + r) * DMODEL + h * DHEAD + c8);
        *(float4*)&Ql[r * LDQ + c8] =
            *(const float4*)(Ql_g + (rowbase + r) * DMODEL + h * DHEAD + c8);
    }

    for (int kb = 0; kb <= qb; kb++) {
        __syncthreads();  // prev iter consumed (also orders Q on iter 0)

        size_t kbase = (size_t)b * TSEQ + (size_t)kb * 64;
        for (int i = tid; i < 64 * 16; i += 512) {
            int r = i >> 4, c8 = (i & 15) * 8;
            size_t gofs = (kbase + r) * DMODEL + h * DHEAD + c8;
            *(float4*)&Kh[r * LDQ + c8] = *(const float4*)(Kh_g + gofs);
            *(float4*)&Kl[r * LDQ + c8] = *(const float4*)(Kl_g + gofs);
            *(float4*)&Vh[r * LDQ + c8] = *(const float4*)(Vh_g + gofs);
            *(float4*)&Vl[r * LDQ + c8] = *(const float4*)(Vl_g + gofs);
        }
        __syncthreads();

        // ---- S = Q K^T (warp tile 16 x 16) ----
        {
            nvcuda::wmma::fragment<nvcuda::wmma::accumulator, 16, 16, 16, float> sacc;
            nvcuda::wmma::fill_fragment(sacc, 0.0f);
#pragma unroll
            for (int k8 = 0; k8 < 8; k8++) {
                nvcuda::wmma::fragment<nvcuda::wmma::matrix_a, 16, 16, 16,
                    __nv_bfloat16, nvcuda::wmma::row_major> aH, aL;
                nvcuda::wmma::load_matrix_sync(aH, &Qh[(wm*16)*LDQ + k8*16], LDQ);
                nvcuda::wmma::load_matrix_sync(aL, &Ql[(wm*16)*LDQ + k8*16], LDQ);
                nvcuda::wmma::fragment<nvcuda::wmma::matrix_b, 16, 16, 16,
                    __nv_bfloat16, nvcuda::wmma::col_major> bF;
                nvcuda::wmma::load_matrix_sync(bF, &Kh[(wn*16)*LDQ + k8*16], LDQ);
                nvcuda::wmma::mma_sync(sacc, aH, bF, sacc);
                nvcuda::wmma::mma_sync(sacc, aL, bF, sacc);
                nvcuda::wmma::load_matrix_sync(bF, &Kl[(wn*16)*LDQ + k8*16], LDQ);
                nvcuda::wmma::mma_sync(sacc, aH, bF, sacc);
            }
            nvcuda::wmma::store_matrix_sync(&Ss[(wm*16)*SPF + wn*16], sacc, SPF,
                                            nvcuda::wmma::mem_row_major);
        }
        __syncthreads();

        // ---- online softmax (warp w: rows w*4..w*4+3) ----
#pragma unroll
        for (int i = 0; i < 4; i++) {
            int r = w * 4 + i;
            int qglob = qb * 64 + r;
            int kg0 = kb * 64 + lane;
            float s0 = (kg0      <= qglob) ? Ss[r * SPF + lane]      : -1e30f;
            float s1 = (kg0 + 32 <= qglob) ? Ss[r * SPF + lane + 32] : -1e30f;
            float tmax = fmaxf(s0, s1);
#pragma unroll
            for (int off = 16; off; off >>= 1)
                tmax = fmaxf(tmax, __shfl_xor_sync(0xffffffffu, tmax, off));
            float mnew = fmaxf(m[i], tmax);
            float p0 = __expf(s0 - mnew);
            float p1 = __expf(s1 - mnew);
            float alpha = __expf(m[i] - mnew);
            float ps = p0 + p1;
#pragma unroll
            for (int off = 16; off; off >>= 1)
                ps += __shfl_xor_sync(0xffffffffu, ps, off);
            l[i] = l[i] * alpha + ps;
            m[i] = mnew;
            __nv_bfloat16 h0 = __float2bfloat16_rn(p0);
            __nv_bfloat16 h1 = __float2bfloat16_rn(p1);
            Ph[r * LDP + lane]      = h0;
            Ph[r * LDP + lane + 32] = h1;
            Pl[r * LDP + lane]      = __float2bfloat16_rn(p0 - __bfloat162float(h0));
            Pl[r * LDP + lane + 32] = __float2bfloat16_rn(p1 - __bfloat162float(h1));
            if (lane == 0) salpha[r] = alpha;
        }
        __syncthreads();

        // ---- Ot = P V (warp tile 16 x 32) ----
        {
            nvcuda::wmma::fragment<nvcuda::wmma::accumulator, 16, 16, 16, float> oacc[2];
#pragma unroll
            for (int j = 0; j < 2; j++) nvcuda::wmma::fill_fragment(oacc[j], 0.0f);
#pragma unroll
            for (int k4 = 0; k4 < 4; k4++) {
                nvcuda::wmma::fragment<nvcuda::wmma::matrix_a, 16, 16, 16,
                    __nv_bfloat16, nvcuda::wmma::row_major> aH, aL;
                nvcuda::wmma::load_matrix_sync(aH, &Ph[(wm*16)*LDP + k4*16], LDP);
                nvcuda::wmma::load_matrix_sync(aL, &Pl[(wm*16)*LDP + k4*16], LDP);
#pragma unroll
                for (int j = 0; j < 2; j++) {
                    nvcuda::wmma::fragment<nvcuda::wmma::matrix_b, 16, 16, 16,
                        __nv_bfloat16, nvcuda::wmma::row_major> bF;
                    nvcuda::wmma::load_matrix_sync(bF,
                        &Vh[(k4*16)*LDQ + wn*32 + j*16], LDQ);
                    nvcuda::wmma::mma_sync(oacc[j], aH, bF, oacc[j]);
                    nvcuda::wmma::mma_sync(oacc[j], aL, bF, oacc[j]);
                    nvcuda::wmma::load_matrix_sync(bF,
                        &Vl[(k4*16)*LDQ + wn*32 + j*16], LDQ);
                    nvcuda::wmma::mma_sync(oacc[j], aH, bF, oacc[j]);
                }
            }
#pragma unroll
            for (int j = 0; j < 2; j++) {
                nvcuda::wmma::store_matrix_sync(
                    &Ss[(wm*16)*SPF + wn*32 + j*16], oacc[j], SPF,
                    nvcuda::wmma::mem_row_major);
            }
        }
        __syncthreads();

        // ---- O = O*alpha + Ot ----
        {
            float a = salpha[orow];
#pragma unroll
            for (int j4 = 0; j4 < 4; j4++) {
                float4 t = *(float4*)&Ss[orow * SPF + ocol + j4 * 4];
                O[j4*4+0] = O[j4*4+0] * a + t.x;
                O[j4*4+1] = O[j4*4+1] * a + t.y;
                O[j4*4+2] = O[j4*4+2] * a + t.z;
                O[j4*4+3] = O[j4*4+3] * a + t.w;
            }
        }
    }

    if (lane == 0) {
#pragma unroll
        for (int i = 0; i < 4; i++) sl[w * 4 + i] = 1.0f / l[i];
    }
    __syncthreads();

    // epilogue: normalize + bf16 hi/lo split (ctx layout [b,t,d])
    {
        float inv = sl[orow];
        size_t gbase = (rowbase + orow) * DMODEL + h * DHEAD + ocol;
#pragma unroll
        for (int j = 0; j < 8; j++) {
            float v0 = O[2*j]   * inv;
            float v1 = O[2*j+1] * inv;
            __nv_bfloat16 h0 = __float2bfloat16_rn(v0);
            __nv_bfloat16 h1 = __float2bfloat16_rn(v1);
            __nv_bfloat162 hp; hp.x = h0; hp.y = h1;
            __nv_bfloat162 lp;
            lp.x = __float2bfloat16_rn(v0 - __bfloat162float(h0));
            lp.y = __float2bfloat16_rn(v1 - __bfloat162float(h1));
            *(__nv_bfloat162*)(Chi + gbase + 2*j) = hp;
            *(__nv_bfloat162*)(Clo + gbase + 2*j) = lp;
        }
    }
}

// ---------------------------------------------------------------------------
extern "C" void kernel_launch(void* const* d_in, const int* in_sizes, int n_in,
                              void* d_out, int out_size)
{
    const float* x  = (const float*)d_in[0];
    const float* qw = (const float*)d_in[1];
    const float* kw = (const float*)d_in[2];
    const float* vw = (const float*)d_in[3];
    const float* ww = (const float*)d_in[4];
    const int* pos  = (const int*)d_in[5];
    float* out = (float*)d_out;

    float *Qb, *Kb, *Vb;
    cudaGetSymbolAddress((void**)&Qb, g_Q);
    cudaGetSymbolAddress((void**)&Kb, g_K);
    cudaGetSymbolAddress((void**)&Vb, g_V);

    __nv_bfloat16 *xhi, *xlo, *chi, *clo;
    __nv_bfloat16 *qh, *ql, *kh, *kl, *vh, *vl;
    __nv_bfloat16 *wqh, *wql, *wkh, *wkl, *wvh, *wvl, *woh, *wol;
    cudaGetSymbolAddress((void**)&xhi, g_xhi);
    cudaGetSymbolAddress((void**)&xlo, g_xlo);
    cudaGetSymbolAddress((void**)&chi, g_chi);
    cudaGetSymbolAddress((void**)&clo, g_clo);
    cudaGetSymbolAddress((void**)&qh, g_qh);
    cudaGetSymbolAddress((void**)&ql, g_ql);
    cudaGetSymbolAddress((void**)&kh, g_kh);
    cudaGetSymbolAddress((void**)&kl, g_kl);
    cudaGetSymbolAddress((void**)&vh, g_vh);
    cudaGetSymbolAddress((void**)&vl, g_vl);
    cudaGetSymbolAddress((void**)&wqh, g_wqhi);
    cudaGetSymbolAddress((void**)&wql, g_wqlo);
    cudaGetSymbolAddress((void**)&wkh, g_wkhi);
    cudaGetSymbolAddress((void**)&wkl, g_wklo);
    cudaGetSymbolAddress((void**)&wvh, g_wvhi);
    cudaGetSymbolAddress((void**)&wvl, g_wvlo);
    cudaGetSymbolAddress((void**)&woh, g_wohi);
    cudaGetSymbolAddress((void**)&wol, g_wolo);

    const int xn4 = MTOT * DMODEL / 4;
    const int wn4 = DMODEL * DMODEL / 4;
    split_kernel<<<(xn4 + 255) / 256, 256>>>(x,  xhi, xlo, xn4);
    split_kernel<<<(wn4 + 255) / 256, 256>>>(qw, wqh, wql, wn4);
    split_kernel<<<(wn4 + 255) / 256, 256>>>(kw, wkh, wkl, wn4);
    split_kernel<<<(wn4 + 255) / 256, 256>>>(vw, wvh, wvl, wn4);
    split_kernel<<<(wn4 + 255) / 256, 256>>>(ww, woh, wol, wn4);

    dim3 gg(DMODEL / 128, MTOT / 128);
    bf16x3_gemm<<<gg, 256>>>(xhi, xlo, wqh, wql, Qb, MTOT, DMODEL, DMODEL);
    bf16x3_gemm<<<gg, 256>>>(xhi, xlo, wkh, wkl, Kb, MTOT, DMODEL, DMODEL);
    bf16x3_gemm<<<gg, 256>>>(xhi, xlo, wvh, wvl, Vb, MTOT, DMODEL, DMODEL);

    int ropeN = 2 * BATCH * TSEQ * NHEAD * 64;
    rope_split_kernel<<<(ropeN + 255) / 256, 256>>>(Qb, Kb, qh, ql, kh, kl, pos);
    split_kernel<<<(xn4 + 255) / 256, 256>>>(Vb, vh, vl, xn4);

    cudaFuncSetAttribute(attn_mma_kernel,
                         cudaFuncAttributeMaxDynamicSharedMemorySize, ATT_SMEM);
    dim3 ga(TSEQ / 64, BATCH * NHEAD);
    attn_mma_kernel<<<ga, 512, ATT_SMEM>>>(qh, ql, kh, kl, vh, vl, chi, clo);

    bf16x3_gemm<<<gg, 256>>>(chi, clo, woh, wol, out, MTOT, DMODEL, DMODEL);
}

// round 12
// speedup vs baseline: 3.2078x; 1.2757x over previous
#include <cuda_runtime.h>
#include <cuda_bf16.h>
#include <cuda_pipeline.h>
#include <mma.h>
#include <math.h>

#define BATCH 2
#define TSEQ 2048
#define DMODEL 2048
#define NHEAD 16
#define DHEAD 128
#define MTOT (BATCH*TSEQ)
#define NQKV (3*DMODEL)

// ---------------- scratch (__device__ globals; no allocs allowed) ----------
__device__ float g_Q[MTOT*DMODEL];
__device__ float g_K[MTOT*DMODEL];
__device__ float g_V[MTOT*DMODEL];

__device__ __nv_bfloat16 g_xhi[MTOT*DMODEL];
__device__ __nv_bfloat16 g_xlo[MTOT*DMODEL];
__device__ __nv_bfloat16 g_chi[MTOT*DMODEL];
__device__ __nv_bfloat16 g_clo[MTOT*DMODEL];
__device__ __nv_bfloat16 g_qh[MTOT*DMODEL];
__device__ __nv_bfloat16 g_ql[MTOT*DMODEL];
__device__ __nv_bfloat16 g_kh[MTOT*DMODEL];
__device__ __nv_bfloat16 g_kl[MTOT*DMODEL];
__device__ __nv_bfloat16 g_vh[MTOT*DMODEL];
__device__ __nv_bfloat16 g_vl[MTOT*DMODEL];
__device__ __nv_bfloat16 g_wqkvh[DMODEL*NQKV];
__device__ __nv_bfloat16 g_wqkvl[DMODEL*NQKV];
__device__ __nv_bfloat16 g_wohi[DMODEL*DMODEL];
__device__ __nv_bfloat16 g_wolo[DMODEL*DMODEL];

// ---------------------------------------------------------------------------
// split fp32 -> bf16 hi + lo (contiguous)
// ---------------------------------------------------------------------------
__global__ void split_kernel(const float* __restrict__ in,
                             __nv_bfloat16* __restrict__ hi,
                             __nv_bfloat16* __restrict__ lo, int n4)
{
    int i = blockIdx.x * blockDim.x + threadIdx.x;
    if (i >= n4) return;
    float4 v = ((const float4*)in)[i];
    __nv_bfloat16 h0 = __float2bfloat16_rn(v.x);
    __nv_bfloat16 h1 = __float2bfloat16_rn(v.y);
    __nv_bfloat16 h2 = __float2bfloat16_rn(v.z);
    __nv_bfloat16 h3 = __float2bfloat16_rn(v.w);
    __nv_bfloat162 ha; ha.x = h0; ha.y = h1;
    __nv_bfloat162 hb; hb.x = h2; hb.y = h3;
    __nv_bfloat162 la;
    la.x = __float2bfloat16_rn(v.x - __bfloat162float(h0));
    la.y = __float2bfloat16_rn(v.y - __bfloat162float(h1));
    __nv_bfloat162 lb;
    lb.x = __float2bfloat16_rn(v.z - __bfloat162float(h2));
    lb.y = __float2bfloat16_rn(v.w - __bfloat162float(h3));
    ((__nv_bfloat162*)hi)[2*i]   = ha;
    ((__nv_bfloat162*)hi)[2*i+1] = hb;
    ((__nv_bfloat162*)lo)[2*i]   = la;
    ((__nv_bfloat162*)lo)[2*i+1] = lb;
}

// ---------------------------------------------------------------------------
// split fp32 [2048x2048] -> packed bf16 hi/lo at column offset (row stride 6144)
// ---------------------------------------------------------------------------
__global__ void split_pack_kernel(const float* __restrict__ in,
                                  __nv_bfloat16* __restrict__ hi,
                                  __nv_bfloat16* __restrict__ lo, int colofs)
{
    int i = blockIdx.x * blockDim.x + threadIdx.x;
    if (i >= DMODEL * (DMODEL / 4)) return;
    float4 v = ((const float4*)in)[i];
    int row = i >> 9;
    int c4  = (i & 511) * 4;
    size_t d = (size_t)row * NQKV + colofs + c4;
    __nv_bfloat16 h0 = __float2bfloat16_rn(v.x);
    __nv_bfloat16 h1 = __float2bfloat16_rn(v.y);
    __nv_bfloat16 h2 = __float2bfloat16_rn(v.z);
    __nv_bfloat16 h3 = __float2bfloat16_rn(v.w);
    __nv_bfloat162 ha; ha.x = h0; ha.y = h1;
    __nv_bfloat162 hb; hb.x = h2; hb.y = h3;
    __nv_bfloat162 la;
    la.x = __float2bfloat16_rn(v.x - __bfloat162float(h0));
    la.y = __float2bfloat16_rn(v.y - __bfloat162float(h1));
    __nv_bfloat162 lb;
    lb.x = __float2bfloat16_rn(v.z - __bfloat162float(h2));
    lb.y = __float2bfloat16_rn(v.w - __bfloat162float(h3));
    *(__nv_bfloat162*)(hi + d)     = ha;
    *(__nv_bfloat162*)(hi + d + 2) = hb;
    *(__nv_bfloat162*)(lo + d)     = la;
    *(__nv_bfloat162*)(lo + d + 2) = lb;
}

// ---------------------------------------------------------------------------
// fused RoPE + bf16 split for Q (pre-scaled) and K
// ---------------------------------------------------------------------------
__global__ void rope_split_kernel(const float* __restrict__ Q,
                                  const float* __restrict__ K,
                                  __nv_bfloat16* __restrict__ Qh,
                                  __nv_bfloat16* __restrict__ Ql,
                                  __nv_bfloat16* __restrict__ Kh,
                                  __nv_bfloat16* __restrict__ Kl,
                                  const int* __restrict__ posp)
{
    const int total = BATCH * TSEQ * NHEAD * 64;
    int idx = blockIdx.x * blockDim.x + threadIdx.x;
    if (idx >= 2 * total) return;
    const bool isq = (idx < total);
    int e = isq ? idx : idx - total;
    int j = e & 63;
    int h = (e >> 6) & (NHEAD - 1);
    int t = (e >> 10) & (TSEQ - 1);
    int b = e >> 21;
    int p0 = *posp; if (p0 < 0) p0 = 0;
    float inv = __expf(-0.14391156463f * (float)j);
    float ang = (float)(p0 + t) * inv;
    float s, c;
    sincosf(ang, &s, &c);
    size_t base = ((size_t)(b * TSEQ + t)) * DMODEL + h * DHEAD + j;
    const float* src = isq ? Q : K;
    float x1 = src[base], x2 = src[base + 64];
    float y1 = x1 * c - x2 * s;
    float y2 = x1 * s + x2 * c;
    if (isq) {
        const float sc = 0.08838834764831845f;
        y1 *= sc; y2 *= sc;
    }
    __nv_bfloat16* hi = isq ? Qh : Kh;
    __nv_bfloat16* lo = isq ? Ql : Kl;
    __nv_bfloat16 h1 = __float2bfloat16_rn(y1);
    __nv_bfloat16 h2 = __float2bfloat16_rn(y2);
    hi[base]      = h1;
    hi[base + 64] = h2;
    lo[base]      = __float2bfloat16_rn(y1 - __bfloat162float(h1));
    lo[base + 64] = __float2bfloat16_rn(y2 - __bfloat162float(h2));
}

// ---------------------------------------------------------------------------
// 3-term bf16 GEMM, warp tile 64x64, block 128x256, BK=32, cp.async 2-stage.
// C tiles (256 cols each) routed to C0/C1/C2 by bx>>3.
// ---------------------------------------------------------------------------
#define GLDA 40
#define GLDB 264
#define ASZ (128*GLDA)   // elems per A tensor per stage
#define BSZ (32*GLDB)    // elems per B tensor per stage
#define GEMM_SMEM ((4*ASZ + 4*BSZ) * 2)

__device__ __forceinline__ void qload(
    __nv_bfloat16* sAh, __nv_bfloat16* sAl,
    __nv_bfloat16* sBh, __nv_bfloat16* sBl,
    const __nv_bfloat16* gAh, const __nv_bfloat16* gAl,
    const __nv_bfloat16* gBh, const __nv_bfloat16* gBl,
    int tid, int k0, int K, int ldb)
{
#pragma unroll
    for (int t = 0; t < 2; t++) {
        int c = tid + t * 256;
        int r = c >> 2, kc = (c & 3) * 8;
        __pipeline_memcpy_async(&sAh[r*GLDA + kc], gAh + (size_t)r*K + k0 + kc, 16);
        __pipeline_memcpy_async(&sAl[r*GLDA + kc], gAl + (size_t)r*K + k0 + kc, 16);
    }
#pragma unroll
    for (int t = 0; t < 4; t++) {
        int c = tid + t * 256;
        int kr = c >> 5, nc = (c & 31) * 8;
        __pipeline_memcpy_async(&sBh[kr*GLDB + nc], gBh + (size_t)(k0+kr)*ldb + nc, 16);
        __pipeline_memcpy_async(&sBl[kr*GLDB + nc], gBl + (size_t)(k0+kr)*ldb + nc, 16);
    }
    __pipeline_commit();
}

__global__ __launch_bounds__(256, 1) void qkv_gemm(
    const __nv_bfloat16* __restrict__ Ah, const __nv_bfloat16* __restrict__ Al,
    const __nv_bfloat16* __restrict__ Bh, const __nv_bfloat16* __restrict__ Bl,
    float* __restrict__ C0, float* __restrict__ C1, float* __restrict__ C2,
    int K, int ldb)
{
    extern __shared__ __nv_bfloat16 smg[];
    __nv_bfloat16* SA_h = smg;                 // [2][ASZ]
    __nv_bfloat16* SA_l = smg + 2*ASZ;
    __nv_bfloat16* SB_h = smg + 4*ASZ;         // [2][BSZ]
    __nv_bfloat16* SB_l = smg + 4*ASZ + 2*BSZ;

    const int tid  = threadIdx.x;
    const int warp = tid >> 5;
    const int wm   = warp >> 2;   // 0..1 (64-row slab)
    const int wn   = warp & 3;    // 0..3 (64-col slab)
    const int bx   = blockIdx.x, by = blockIdx.y;

    const __nv_bfloat16* gAh = Ah + (size_t)by * 128 * K;
    const __nv_bfloat16* gAl = Al + (size_t)by * 128 * K;
    const __nv_bfloat16* gBh = Bh + (size_t)bx * 256;
    const __nv_bfloat16* gBl = Bl + (size_t)bx * 256;

    nvcuda::wmma::fragment<nvcuda::wmma::accumulator, 16, 16, 16, float> acc[4][4];
#pragma unroll
    for (int i = 0; i < 4; i++) {
#pragma unroll
        for (int j = 0; j < 4; j++) nvcuda::wmma::fill_fragment(acc[i][j], 0.0f);
    }

    qload(SA_h, SA_l, SB_h, SB_l, gAh, gAl, gBh, gBl, tid, 0, K, ldb);

    const int NK = K / 32;
    for (int kt = 0; kt < NK; kt++) {
        const int st = kt & 1;
        const bool more = (kt + 1 < NK);
        if (more) {
            qload(SA_h + (st^1)*ASZ, SA_l + (st^1)*ASZ,
                  SB_h + (st^1)*BSZ, SB_l + (st^1)*BSZ,
                  gAh, gAl, gBh, gBl, tid, (kt + 1) * 32, K, ldb);
        }
        if (more) __pipeline_wait_prior(1);
        else      __pipeline_wait_prior(0);
        __syncthreads();

        const __nv_bfloat16* Ah_s = SA_h + st*ASZ;
        const __nv_bfloat16* Al_s = SA_l + st*ASZ;
        const __nv_bfloat16* Bh_s = SB_h + st*BSZ;
        const __nv_bfloat16* Bl_s = SB_l + st*BSZ;

#pragma unroll
        for (int ks = 0; ks < 2; ks++) {
            nvcuda::wmma::fragment<nvcuda::wmma::matrix_b, 16, 16, 16,
                __nv_bfloat16, nvcuda::wmma::row_major> bH[4], bL[4];
#pragma unroll
            for (int j = 0; j < 4; j++) {
                nvcuda::wmma::load_matrix_sync(bH[j],
                    &Bh_s[ks*16*GLDB + wn*64 + j*16], GLDB);
            }
#pragma unroll
            for (int j = 0; j < 4; j++) {
                nvcuda::wmma::load_matrix_sync(bL[j],
                    &Bl_s[ks*16*GLDB + wn*64 + j*16], GLDB);
            }
#pragma unroll
            for (int i = 0; i < 4; i++) {
                nvcuda::wmma::fragment<nvcuda::wmma::matrix_a, 16, 16, 16,
                    __nv_bfloat16, nvcuda::wmma::row_major> aH, aL;
                nvcuda::wmma::load_matrix_sync(aH,
                    &Ah_s[(wm*64 + i*16)*GLDA + ks*16], GLDA);
                nvcuda::wmma::load_matrix_sync(aL,
                    &Al_s[(wm*64 + i*16)*GLDA + ks*16], GLDA);
#pragma unroll
                for (int j = 0; j < 4; j++) {
                    nvcuda::wmma::mma_sync(acc[i][j], aH, bH[j], acc[i][j]);
                    nvcuda::wmma::mma_sync(acc[i][j], aL, bH[j], acc[i][j]);
                    nvcuda::wmma::mma_sync(acc[i][j], aH, bL[j], acc[i][j]);
                }
            }
        }
        __syncthreads();
    }

    // epilogue: route tile to the right output region
    const int region = bx >> 3;
    float* Cp = (region == 0) ? C0 : ((region == 1) ? C1 : C2);
    const int colbase = (bx & 7) * 256;
#pragma unroll
    for (int i = 0; i < 4; i++) {
#pragma unroll
        for (int j = 0; j < 4; j++) {
            size_t row = (size_t)by * 128 + wm*64 + i*16;
            int col = colbase + wn*64 + j*16;
            nvcuda::wmma::store_matrix_sync(
                Cp + row * DMODEL + col, acc[i][j], DMODEL,
                nvcuda::wmma::mem_row_major);
        }
    }
}

// ---------------------------------------------------------------------------
// Flash attention, tensor cores, pre-split bf16 inputs. 512 thr = 16 warps.
// (unchanged from R11)
// ---------------------------------------------------------------------------
#define SPF 136
#define LDQ 136
#define LDP 72

#define OFF_SS   0
#define OFF_QH   (64*SPF*4)
#define OFF_QL   (OFF_QH + 64*LDQ*2)
#define OFF_KH   (OFF_QL + 64*LDQ*2)
#define OFF_KL   (OFF_KH + 64*LDQ*2)
#define OFF_VH   (OFF_KL + 64*LDQ*2)
#define OFF_VL   (OFF_VH + 64*LDQ*2)
#define OFF_PH   (OFF_VL + 64*LDQ*2)
#define OFF_PL   (OFF_PH + 64*LDP*2)
#define OFF_AL   (OFF_PL + 64*LDP*2)
#define OFF_LL   (OFF_AL + 64*4)
#define ATT_SMEM (OFF_LL + 64*4)

__global__ __launch_bounds__(512) void attn_mma_kernel(
    const __nv_bfloat16* __restrict__ Qh_g, const __nv_bfloat16* __restrict__ Ql_g,
    const __nv_bfloat16* __restrict__ Kh_g, const __nv_bfloat16* __restrict__ Kl_g,
    const __nv_bfloat16* __restrict__ Vh_g, const __nv_bfloat16* __restrict__ Vl_g,
    __nv_bfloat16* __restrict__ Chi, __nv_bfloat16* __restrict__ Clo)
{
    extern __shared__ char smc[];
    float*         Ss = (float*)(smc + OFF_SS);
    __nv_bfloat16* Qh = (__nv_bfloat16*)(smc + OFF_QH);
    __nv_bfloat16* Ql = (__nv_bfloat16*)(smc + OFF_QL);
    __nv_bfloat16* Kh = (__nv_bfloat16*)(smc + OFF_KH);
    __nv_bfloat16* Kl = (__nv_bfloat16*)(smc + OFF_KL);
    __nv_bfloat16* Vh = (__nv_bfloat16*)(smc + OFF_VH);
    __nv_bfloat16* Vl = (__nv_bfloat16*)(smc + OFF_VL);
    __nv_bfloat16* Ph = (__nv_bfloat16*)(smc + OFF_PH);
    __nv_bfloat16* Pl = (__nv_bfloat16*)(smc + OFF_PL);
    float*     salpha = (float*)(smc + OFF_AL);
    float*         sl = (float*)(smc + OFF_LL);

    const int tid  = threadIdx.x;
    const int lane = tid & 31, w = tid >> 5;
    const int wm   = w >> 2, wn = w & 3;
    const int qb   = gridDim.x - 1 - blockIdx.x;
    const int bh   = blockIdx.y;
    const int b    = bh >> 4, h = bh & (NHEAD - 1);
    const size_t rowbase = (size_t)b * TSEQ + (size_t)qb * 64;

    const int orow = tid >> 3;
    const int ocol = (tid & 7) * 16;
    float O[16];
#pragma unroll
    for (int i = 0; i < 16; i++) O[i] = 0.f;

    float m[4], l[4];
#pragma unroll
    for (int i = 0; i < 4; i++) { m[i] = -1e30f; l[i] = 0.f; }

    for (int i = tid; i < 64 * 16; i += 512) {
        int r = i >> 4, c8 = (i & 15) * 8;
        *(float4*)&Qh[r * LDQ + c8] =
            *(const float4*)(Qh_g + (rowbase + r) * DMODEL + h * DHEAD + c8);
        *(float4*)&Ql[r * LDQ + c8] =
            *(const float4*)(Ql_g + (rowbase + r) * DMODEL + h * DHEAD + c8);
    }

    for (int kb = 0; kb <= qb; kb++) {
        __syncthreads();

        size_t kbase = (size_t)b * TSEQ + (size_t)kb * 64;
        for (int i = tid; i < 64 * 16; i += 512) {
            int r = i >> 4, c8 = (i & 15) * 8;
            size_t gofs = (kbase + r) * DMODEL + h * DHEAD + c8;
            *(float4*)&Kh[r * LDQ + c8] = *(const float4*)(Kh_g + gofs);
            *(float4*)&Kl[r * LDQ + c8] = *(const float4*)(Kl_g + gofs);
            *(float4*)&Vh[r * LDQ + c8] = *(const float4*)(Vh_g + gofs);
            *(float4*)&Vl[r * LDQ + c8] = *(const float4*)(Vl_g + gofs);
        }
        __syncthreads();

        {
            nvcuda::wmma::fragment<nvcuda::wmma::accumulator, 16, 16, 16, float> sacc;
            nvcuda::wmma::fill_fragment(sacc, 0.0f);
#pragma unroll
            for (int k8 = 0; k8 < 8; k8++) {
                nvcuda::wmma::fragment<nvcuda::wmma::matrix_a, 16, 16, 16,
                    __nv_bfloat16, nvcuda::wmma::row_major> aH, aL;
                nvcuda::wmma::load_matrix_sync(aH, &Qh[(wm*16)*LDQ + k8*16], LDQ);
                nvcuda::wmma::load_matrix_sync(aL, &Ql[(wm*16)*LDQ + k8*16], LDQ);
                nvcuda::wmma::fragment<nvcuda::wmma::matrix_b, 16, 16, 16,
                    __nv_bfloat16, nvcuda::wmma::col_major> bF;
                nvcuda::wmma::load_matrix_sync(bF, &Kh[(wn*16)*LDQ + k8*16], LDQ);
                nvcuda::wmma::mma_sync(sacc, aH, bF, sacc);
                nvcuda::wmma::mma_sync(sacc, aL, bF, sacc);
                nvcuda::wmma::load_matrix_sync(bF, &Kl[(wn*16)*LDQ + k8*16], LDQ);
                nvcuda::wmma::mma_sync(sacc, aH, bF, sacc);
            }
            nvcuda::wmma::store_matrix_sync(&Ss[(wm*16)*SPF + wn*16], sacc, SPF,
                                            nvcuda::wmma::mem_row_major);
        }
        __syncthreads();

#pragma unroll
        for (int i = 0; i < 4; i++) {
            int r = w * 4 + i;
            int qglob = qb * 64 + r;
            int kg0 = kb * 64 + lane;
            float s0 = (kg0      <= qglob) ? Ss[r * SPF + lane]      : -1e30f;
            float s1 = (kg0 + 32 <= qglob) ? Ss[r * SPF + lane + 32] : -1e30f;
            float tmax = fmaxf(s0, s1);
#pragma unroll
            for (int off = 16; off; off >>= 1)
                tmax = fmaxf(tmax, __shfl_xor_sync(0xffffffffu, tmax, off));
            float mnew = fmaxf(m[i], tmax);
            float p0 = __expf(s0 - mnew);
            float p1 = __expf(s1 - mnew);
            float alpha = __expf(m[i] - mnew);
            float ps = p0 + p1;
#pragma unroll
            for (int off = 16; off; off >>= 1)
                ps += __shfl_xor_sync(0xffffffffu, ps, off);
            l[i] = l[i] * alpha + ps;
            m[i] = mnew;
            __nv_bfloat16 h0 = __float2bfloat16_rn(p0);
            __nv_bfloat16 h1 = __float2bfloat16_rn(p1);
            Ph[r * LDP + lane]      = h0;
            Ph[r * LDP + lane + 32] = h1;
            Pl[r * LDP + lane]      = __float2bfloat16_rn(p0 - __bfloat162float(h0));
            Pl[r * LDP + lane + 32] = __float2bfloat16_rn(p1 - __bfloat162float(h1));
            if (lane == 0) salpha[r] = alpha;
        }
        __syncthreads();

        {
            nvcuda::wmma::fragment<nvcuda::wmma::accumulator, 16, 16, 16, float> oacc[2];
#pragma unroll
            for (int j = 0; j < 2; j++) nvcuda::wmma::fill_fragment(oacc[j], 0.0f);
#pragma unroll
            for (int k4 = 0; k4 < 4; k4++) {
                nvcuda::wmma::fragment<nvcuda::wmma::matrix_a, 16, 16, 16,
                    __nv_bfloat16, nvcuda::wmma::row_major> aH, aL;
                nvcuda::wmma::load_matrix_sync(aH, &Ph[(wm*16)*LDP + k4*16], LDP);
                nvcuda::wmma::load_matrix_sync(aL, &Pl[(wm*16)*LDP + k4*16], LDP);
#pragma unroll
                for (int j = 0; j < 2; j++) {
                    nvcuda::wmma::fragment<nvcuda::wmma::matrix_b, 16, 16, 16,
                        __nv_bfloat16, nvcuda::wmma::row_major> bF;
                    nvcuda::wmma::load_matrix_sync(bF,
                        &Vh[(k4*16)*LDQ + wn*32 + j*16], LDQ);
                    nvcuda::wmma::mma_sync(oacc[j], aH, bF, oacc[j]);
                    nvcuda::wmma::mma_sync(oacc[j], aL, bF, oacc[j]);
                    nvcuda::wmma::load_matrix_sync(bF,
                        &Vl[(k4*16)*LDQ + wn*32 + j*16], LDQ);
                    nvcuda::wmma::mma_sync(oacc[j], aH, bF, oacc[j]);
                }
            }
#pragma unroll
            for (int j = 0; j < 2; j++) {
                nvcuda::wmma::store_matrix_sync(
                    &Ss[(wm*16)*SPF + wn*32 + j*16], oacc[j], SPF,
                    nvcuda::wmma::mem_row_major);
            }
        }
        __syncthreads();

        {
            float a = salpha[orow];
#pragma unroll
            for (int j4 = 0; j4 < 4; j4++) {
                float4 t = *(float4*)&Ss[orow * SPF + ocol + j4 * 4];
                O[j4*4+0] = O[j4*4+0] * a + t.x;
                O[j4*4+1] = O[j4*4+1] * a + t.y;
                O[j4*4+2] = O[j4*4+2] * a + t.z;
                O[j4*4+3] = O[j4*4+3] * a + t.w;
            }
        }
    }

    if (lane == 0) {
#pragma unroll
        for (int i = 0; i < 4; i++) sl[w * 4 + i] = 1.0f / l[i];
    }
    __syncthreads();

    {
        float inv = sl[orow];
        size_t gbase = (rowbase + orow) * DMODEL + h * DHEAD + ocol;
#pragma unroll
        for (int j = 0; j < 8; j++) {
            float v0 = O[2*j]   * inv;
            float v1 = O[2*j+1] * inv;
            __nv_bfloat16 h0 = __float2bfloat16_rn(v0);
            __nv_bfloat16 h1 = __float2bfloat16_rn(v1);
            __nv_bfloat162 hp; hp.x = h0; hp.y = h1;
            __nv_bfloat162 lp;
            lp.x = __float2bfloat16_rn(v0 - __bfloat162float(h0));
            lp.y = __float2bfloat16_rn(v1 - __bfloat162float(h1));
            *(__nv_bfloat162*)(Chi + gbase + 2*j) = hp;
            *(__nv_bfloat162*)(Clo + gbase + 2*j) = lp;
        }
    }
}

// ---------------------------------------------------------------------------
extern "C" void kernel_launch(void* const* d_in, const int* in_sizes, int n_in,
                              void* d_out, int out_size)
{
    const float* x  = (const float*)d_in[0];
    const float* qw = (const float*)d_in[1];
    const float* kw = (const float*)d_in[2];
    const float* vw = (const float*)d_in[3];
    const float* ww = (const float*)d_in[4];
    const int* pos  = (const int*)d_in[5];
    float* out = (float*)d_out;

    float *Qb, *Kb, *Vb;
    cudaGetSymbolAddress((void**)&Qb, g_Q);
    cudaGetSymbolAddress((void**)&Kb, g_K);
    cudaGetSymbolAddress((void**)&Vb, g_V);

    __nv_bfloat16 *xhi, *xlo, *chi, *clo;
    __nv_bfloat16 *qh, *ql, *kh, *kl, *vh, *vl;
    __nv_bfloat16 *wqkvh, *wqkvl, *woh, *wol;
    cudaGetSymbolAddress((void**)&xhi, g_xhi);
    cudaGetSymbolAddress((void**)&xlo, g_xlo);
    cudaGetSymbolAddress((void**)&chi, g_chi);
    cudaGetSymbolAddress((void**)&clo, g_clo);
    cudaGetSymbolAddress((void**)&qh, g_qh);
    cudaGetSymbolAddress((void**)&ql, g_ql);
    cudaGetSymbolAddress((void**)&kh, g_kh);
    cudaGetSymbolAddress((void**)&kl, g_kl);
    cudaGetSymbolAddress((void**)&vh, g_vh);
    cudaGetSymbolAddress((void**)&vl, g_vl);
    cudaGetSymbolAddress((void**)&wqkvh, g_wqkvh);
    cudaGetSymbolAddress((void**)&wqkvl, g_wqkvl);
    cudaGetSymbolAddress((void**)&woh, g_wohi);
    cudaGetSymbolAddress((void**)&wol, g_wolo);

    const int xn4 = MTOT * DMODEL / 4;
    const int wn4 = DMODEL * DMODEL / 4;
    split_kernel<<<(xn4 + 255) / 256, 256>>>(x, xhi, xlo, xn4);
    split_pack_kernel<<<(wn4 + 255) / 256, 256>>>(qw, wqkvh, wqkvl, 0);
    split_pack_kernel<<<(wn4 + 255) / 256, 256>>>(kw, wqkvh, wqkvl, DMODEL);
    split_pack_kernel<<<(wn4 + 255) / 256, 256>>>(vw, wqkvh, wqkvl, 2*DMODEL);
    split_kernel<<<(wn4 + 255) / 256, 256>>>(ww, woh, wol, wn4);

    cudaFuncSetAttribute(qkv_gemm,
                         cudaFuncAttributeMaxDynamicSharedMemorySize, GEMM_SMEM);

    dim3 gq(NQKV / 256, MTOT / 128);
    qkv_gemm<<<gq, 256, GEMM_SMEM>>>(xhi, xlo, wqkvh, wqkvl,
                                     Qb, Kb, Vb, DMODEL, NQKV);

    int ropeN = 2 * BATCH * TSEQ * NHEAD * 64;
    rope_split_kernel<<<(ropeN + 255) / 256, 256>>>(Qb, Kb, qh, ql, kh, kl, pos);
    split_kernel<<<(xn4 + 255) / 256, 256>>>(Vb, vh, vl, xn4);

    cudaFuncSetAttribute(attn_mma_kernel,
                         cudaFuncAttributeMaxDynamicSharedMemorySize, ATT_SMEM);
    dim3 ga(TSEQ / 64, BATCH * NHEAD);
    attn_mma_kernel<<<ga, 512, ATT_SMEM>>>(qh, ql, kh, kl, vh, vl, chi, clo);

    dim3 go(DMODEL / 256, MTOT / 128);
    qkv_gemm<<<go, 256, GEMM_SMEM>>>(chi, clo, woh, wol,
                                     out, out, out, DMODEL, DMODEL);
}

// round 13
// speedup vs baseline: 3.3376x; 1.0405x over previous
#include <cuda_runtime.h>
#include <cuda_bf16.h>
#include <cuda_pipeline.h>
#include <mma.h>
#include <math.h>

#define BATCH 2
#define TSEQ 2048
#define DMODEL 2048
#define NHEAD 16
#define DHEAD 128
#define MTOT (BATCH*TSEQ)
#define NQKV (3*DMODEL)

// ---------------- scratch (__device__ globals; no allocs allowed) ----------
__device__ float g_Q[MTOT*DMODEL];
__device__ float g_K[MTOT*DMODEL];
__device__ float g_V[MTOT*DMODEL];

__device__ __nv_bfloat16 g_xhi[MTOT*DMODEL];
__device__ __nv_bfloat16 g_xlo[MTOT*DMODEL];
__device__ __nv_bfloat16 g_chi[MTOT*DMODEL];
__device__ __nv_bfloat16 g_clo[MTOT*DMODEL];
__device__ __nv_bfloat16 g_qh[MTOT*DMODEL];
__device__ __nv_bfloat16 g_ql[MTOT*DMODEL];
__device__ __nv_bfloat16 g_kh[MTOT*DMODEL];
__device__ __nv_bfloat16 g_kl[MTOT*DMODEL];
__device__ __nv_bfloat16 g_vh[MTOT*DMODEL];
__device__ __nv_bfloat16 g_vl[MTOT*DMODEL];
__device__ __nv_bfloat16 g_wqkvh[DMODEL*NQKV];
__device__ __nv_bfloat16 g_wqkvl[DMODEL*NQKV];
__device__ __nv_bfloat16 g_wohi[DMODEL*DMODEL];
__device__ __nv_bfloat16 g_wolo[DMODEL*DMODEL];

// ---------------------------------------------------------------------------
// split fp32 -> bf16 hi + lo (contiguous)
// ---------------------------------------------------------------------------
__global__ void split_kernel(const float* __restrict__ in,
                             __nv_bfloat16* __restrict__ hi,
                             __nv_bfloat16* __restrict__ lo, int n4)
{
    int i = blockIdx.x * blockDim.x + threadIdx.x;
    if (i >= n4) return;
    float4 v = ((const float4*)in)[i];
    __nv_bfloat16 h0 = __float2bfloat16_rn(v.x);
    __nv_bfloat16 h1 = __float2bfloat16_rn(v.y);
    __nv_bfloat16 h2 = __float2bfloat16_rn(v.z);
    __nv_bfloat16 h3 = __float2bfloat16_rn(v.w);
    __nv_bfloat162 ha; ha.x = h0; ha.y = h1;
    __nv_bfloat162 hb; hb.x = h2; hb.y = h3;
    __nv_bfloat162 la;
    la.x = __float2bfloat16_rn(v.x - __bfloat162float(h0));
    la.y = __float2bfloat16_rn(v.y - __bfloat162float(h1));
    __nv_bfloat162 lb;
    lb.x = __float2bfloat16_rn(v.z - __bfloat162float(h2));
    lb.y = __float2bfloat16_rn(v.w - __bfloat162float(h3));
    ((__nv_bfloat162*)hi)[2*i]   = ha;
    ((__nv_bfloat162*)hi)[2*i+1] = hb;
    ((__nv_bfloat162*)lo)[2*i]   = la;
    ((__nv_bfloat162*)lo)[2*i+1] = lb;
}

// ---------------------------------------------------------------------------
// split fp32 [2048x2048] -> packed bf16 hi/lo at column offset (row stride 6144)
// ---------------------------------------------------------------------------
__global__ void split_pack_kernel(const float* __restrict__ in,
                                  __nv_bfloat16* __restrict__ hi,
                                  __nv_bfloat16* __restrict__ lo, int colofs)
{
    int i = blockIdx.x * blockDim.x + threadIdx.x;
    if (i >= DMODEL * (DMODEL / 4)) return;
    float4 v = ((const float4*)in)[i];
    int row = i >> 9;
    int c4  = (i & 511) * 4;
    size_t d = (size_t)row * NQKV + colofs + c4;
    __nv_bfloat16 h0 = __float2bfloat16_rn(v.x);
    __nv_bfloat16 h1 = __float2bfloat16_rn(v.y);
    __nv_bfloat16 h2 = __float2bfloat16_rn(v.z);
    __nv_bfloat16 h3 = __float2bfloat16_rn(v.w);
    __nv_bfloat162 ha; ha.x = h0; ha.y = h1;
    __nv_bfloat162 hb; hb.x = h2; hb.y = h3;
    __nv_bfloat162 la;
    la.x = __float2bfloat16_rn(v.x - __bfloat162float(h0));
    la.y = __float2bfloat16_rn(v.y - __bfloat162float(h1));
    __nv_bfloat162 lb;
    lb.x = __float2bfloat16_rn(v.z - __bfloat162float(h2));
    lb.y = __float2bfloat16_rn(v.w - __bfloat162float(h3));
    *(__nv_bfloat162*)(hi + d)     = ha;
    *(__nv_bfloat162*)(hi + d + 2) = hb;
    *(__nv_bfloat162*)(lo + d)     = la;
    *(__nv_bfloat162*)(lo + d + 2) = lb;
}

// ---------------------------------------------------------------------------
// fused RoPE + bf16 split for Q (pre-scaled) and K
// ---------------------------------------------------------------------------
__global__ void rope_split_kernel(const float* __restrict__ Q,
                                  const float* __restrict__ K,
                                  __nv_bfloat16* __restrict__ Qh,
                                  __nv_bfloat16* __restrict__ Ql,
                                  __nv_bfloat16* __restrict__ Kh,
                                  __nv_bfloat16* __restrict__ Kl,
                                  const int* __restrict__ posp)
{
    const int total = BATCH * TSEQ * NHEAD * 64;
    int idx = blockIdx.x * blockDim.x + threadIdx.x;
    if (idx >= 2 * total) return;
    const bool isq = (idx < total);
    int e = isq ? idx : idx - total;
    int j = e & 63;
    int h = (e >> 6) & (NHEAD - 1);
    int t = (e >> 10) & (TSEQ - 1);
    int b = e >> 21;
    int p0 = *posp; if (p0 < 0) p0 = 0;
    float inv = __expf(-0.14391156463f * (float)j);
    float ang = (float)(p0 + t) * inv;
    float s, c;
    sincosf(ang, &s, &c);
    size_t base = ((size_t)(b * TSEQ + t)) * DMODEL + h * DHEAD + j;
    const float* src = isq ? Q : K;
    float x1 = src[base], x2 = src[base + 64];
    float y1 = x1 * c - x2 * s;
    float y2 = x1 * s + x2 * c;
    if (isq) {
        const float sc = 0.08838834764831845f;
        y1 *= sc; y2 *= sc;
    }
    __nv_bfloat16* hi = isq ? Qh : Kh;
    __nv_bfloat16* lo = isq ? Ql : Kl;
    __nv_bfloat16 h1 = __float2bfloat16_rn(y1);
    __nv_bfloat16 h2 = __float2bfloat16_rn(y2);
    hi[base]      = h1;
    hi[base + 64] = h2;
    lo[base]      = __float2bfloat16_rn(y1 - __bfloat162float(h1));
    lo[base + 64] = __float2bfloat16_rn(y2 - __bfloat162float(h2));
}

// ---------------------------------------------------------------------------
// 3-term bf16 GEMM, warp tile 64x64, block 128x256, BK=32, cp.async 2-stage.
// Term-outer mma ordering: consecutive mma hit different accumulators.
// ---------------------------------------------------------------------------
#define GLDA 40
#define GLDB 264
#define ASZ (128*GLDA)
#define BSZ (32*GLDB)
#define GEMM_SMEM ((4*ASZ + 4*BSZ) * 2)

__device__ __forceinline__ void qload(
    __nv_bfloat16* sAh, __nv_bfloat16* sAl,
    __nv_bfloat16* sBh, __nv_bfloat16* sBl,
    const __nv_bfloat16* gAh, const __nv_bfloat16* gAl,
    const __nv_bfloat16* gBh, const __nv_bfloat16* gBl,
    int tid, int k0, int K, int ldb)
{
#pragma unroll
    for (int t = 0; t < 2; t++) {
        int c = tid + t * 256;
        int r = c >> 2, kc = (c & 3) * 8;
        __pipeline_memcpy_async(&sAh[r*GLDA + kc], gAh + (size_t)r*K + k0 + kc, 16);
        __pipeline_memcpy_async(&sAl[r*GLDA + kc], gAl + (size_t)r*K + k0 + kc, 16);
    }
#pragma unroll
    for (int t = 0; t < 4; t++) {
        int c = tid + t * 256;
        int kr = c >> 5, nc = (c & 31) * 8;
        __pipeline_memcpy_async(&sBh[kr*GLDB + nc], gBh + (size_t)(k0+kr)*ldb + nc, 16);
        __pipeline_memcpy_async(&sBl[kr*GLDB + nc], gBl + (size_t)(k0+kr)*ldb + nc, 16);
    }
    __pipeline_commit();
}

__global__ __launch_bounds__(256, 1) void qkv_gemm(
    const __nv_bfloat16* __restrict__ Ah, const __nv_bfloat16* __restrict__ Al,
    const __nv_bfloat16* __restrict__ Bh, const __nv_bfloat16* __restrict__ Bl,
    float* __restrict__ C0, float* __restrict__ C1, float* __restrict__ C2,
    int K, int ldb)
{
    extern __shared__ __nv_bfloat16 smg[];
    __nv_bfloat16* SA_h = smg;
    __nv_bfloat16* SA_l = smg + 2*ASZ;
    __nv_bfloat16* SB_h = smg + 4*ASZ;
    __nv_bfloat16* SB_l = smg + 4*ASZ + 2*BSZ;

    const int tid  = threadIdx.x;
    const int warp = tid >> 5;
    const int wm   = warp >> 2;
    const int wn   = warp & 3;
    const int bx   = blockIdx.x, by = blockIdx.y;

    const __nv_bfloat16* gAh = Ah + (size_t)by * 128 * K;
    const __nv_bfloat16* gAl = Al + (size_t)by * 128 * K;
    const __nv_bfloat16* gBh = Bh + (size_t)bx * 256;
    const __nv_bfloat16* gBl = Bl + (size_t)bx * 256;

    nvcuda::wmma::fragment<nvcuda::wmma::accumulator, 16, 16, 16, float> acc[4][4];
#pragma unroll
    for (int i = 0; i < 4; i++) {
#pragma unroll
        for (int j = 0; j < 4; j++) nvcuda::wmma::fill_fragment(acc[i][j], 0.0f);
    }

    qload(SA_h, SA_l, SB_h, SB_l, gAh, gAl, gBh, gBl, tid, 0, K, ldb);

    const int NK = K / 32;
    for (int kt = 0; kt < NK; kt++) {
        const int st = kt & 1;
        const bool more = (kt + 1 < NK);
        if (more) {
            qload(SA_h + (st^1)*ASZ, SA_l + (st^1)*ASZ,
                  SB_h + (st^1)*BSZ, SB_l + (st^1)*BSZ,
                  gAh, gAl, gBh, gBl, tid, (kt + 1) * 32, K, ldb);
        }
        if (more) __pipeline_wait_prior(1);
        else      __pipeline_wait_prior(0);
        __syncthreads();

        const __nv_bfloat16* Ah_s = SA_h + st*ASZ;
        const __nv_bfloat16* Al_s = SA_l + st*ASZ;
        const __nv_bfloat16* Bh_s = SB_h + st*BSZ;
        const __nv_bfloat16* Bl_s = SB_l + st*BSZ;

#pragma unroll
        for (int ks = 0; ks < 2; ks++) {
            nvcuda::wmma::fragment<nvcuda::wmma::matrix_b, 16, 16, 16,
                __nv_bfloat16, nvcuda::wmma::row_major> bH[4], bL[4];
#pragma unroll
            for (int j = 0; j < 4; j++) {
                nvcuda::wmma::load_matrix_sync(bH[j],
                    &Bh_s[ks*16*GLDB + wn*64 + j*16], GLDB);
            }
#pragma unroll
            for (int j = 0; j < 4; j++) {
                nvcuda::wmma::load_matrix_sync(bL[j],
                    &Bl_s[ks*16*GLDB + wn*64 + j*16], GLDB);
            }
#pragma unroll
            for (int i = 0; i < 4; i++) {
                nvcuda::wmma::fragment<nvcuda::wmma::matrix_a, 16, 16, 16,
                    __nv_bfloat16, nvcuda::wmma::row_major> aH, aL;
                nvcuda::wmma::load_matrix_sync(aH,
                    &Ah_s[(wm*64 + i*16)*GLDA + ks*16], GLDA);
                nvcuda::wmma::load_matrix_sync(aL,
                    &Al_s[(wm*64 + i*16)*GLDA + ks*16], GLDA);
                // term-outer ordering: consecutive mma -> different acc
#pragma unroll
                for (int j = 0; j < 4; j++)
                    nvcuda::wmma::mma_sync(acc[i][j], aH, bH[j], acc[i][j]);
#pragma unroll
                for (int j = 0; j < 4; j++)
                    nvcuda::wmma::mma_sync(acc[i][j], aL, bH[j], acc[i][j]);
#pragma unroll
                for (int j = 0; j < 4; j++)
                    nvcuda::wmma::mma_sync(acc[i][j], aH, bL[j], acc[i][j]);
            }
        }
        __syncthreads();
    }

    const int region = bx >> 3;
    float* Cp = (region == 0) ? C0 : ((region == 1) ? C1 : C2);
    const int colbase = (bx & 7) * 256;
#pragma unroll
    for (int i = 0; i < 4; i++) {
#pragma unroll
        for (int j = 0; j < 4; j++) {
            size_t row = (size_t)by * 128 + wm*64 + i*16;
            int col = colbase + wn*64 + j*16;
            nvcuda::wmma::store_matrix_sync(
                Cp + row * DMODEL + col, acc[i][j], DMODEL,
                nvcuda::wmma::mem_row_major);
        }
    }
}

// ---------------------------------------------------------------------------
// Flash attention, tensor cores, pre-split bf16 inputs, cp.async prefetch of
// next K (after S) / next V (after PV). 512 thr = 16 warps.
// ---------------------------------------------------------------------------
#define SPF 136
#define LDQ 136
#define LDP 72

#define OFF_SS   0
#define OFF_QH   (64*SPF*4)
#define OFF_QL   (OFF_QH + 64*LDQ*2)
#define OFF_KH   (OFF_QL + 64*LDQ*2)
#define OFF_KL   (OFF_KH + 64*LDQ*2)
#define OFF_VH   (OFF_KL + 64*LDQ*2)
#define OFF_VL   (OFF_VH + 64*LDQ*2)
#define OFF_PH   (OFF_VL + 64*LDQ*2)
#define OFF_PL   (OFF_PH + 64*LDP*2)
#define OFF_AL   (OFF_PL + 64*LDP*2)
#define OFF_LL   (OFF_AL + 64*4)
#define ATT_SMEM (OFF_LL + 64*4)

__device__ __forceinline__ void prefetch_tile(
    __nv_bfloat16* dstH, __nv_bfloat16* dstL,
    const __nv_bfloat16* srcH, const __nv_bfloat16* srcL,
    size_t kbase, int h, int tid)
{
#pragma unroll
    for (int t = 0; t < 2; t++) {
        int i = tid + t * 512;
        int r = i >> 4, c8 = (i & 15) * 8;
        size_t gofs = (kbase + r) * DMODEL + h * DHEAD + c8;
        __pipeline_memcpy_async(&dstH[r * LDQ + c8], srcH + gofs, 16);
        __pipeline_memcpy_async(&dstL[r * LDQ + c8], srcL + gofs, 16);
    }
    __pipeline_commit();
}

__global__ __launch_bounds__(512) void attn_mma_kernel(
    const __nv_bfloat16* __restrict__ Qh_g, const __nv_bfloat16* __restrict__ Ql_g,
    const __nv_bfloat16* __restrict__ Kh_g, const __nv_bfloat16* __restrict__ Kl_g,
    const __nv_bfloat16* __restrict__ Vh_g, const __nv_bfloat16* __restrict__ Vl_g,
    __nv_bfloat16* __restrict__ Chi, __nv_bfloat16* __restrict__ Clo)
{
    extern __shared__ char smc[];
    float*         Ss = (float*)(smc + OFF_SS);
    __nv_bfloat16* Qh = (__nv_bfloat16*)(smc + OFF_QH);
    __nv_bfloat16* Ql = (__nv_bfloat16*)(smc + OFF_QL);
    __nv_bfloat16* Kh = (__nv_bfloat16*)(smc + OFF_KH);
    __nv_bfloat16* Kl = (__nv_bfloat16*)(smc + OFF_KL);
    __nv_bfloat16* Vh = (__nv_bfloat16*)(smc + OFF_VH);
    __nv_bfloat16* Vl = (__nv_bfloat16*)(smc + OFF_VL);
    __nv_bfloat16* Ph = (__nv_bfloat16*)(smc + OFF_PH);
    __nv_bfloat16* Pl = (__nv_bfloat16*)(smc + OFF_PL);
    float*     salpha = (float*)(smc + OFF_AL);
    float*         sl = (float*)(smc + OFF_LL);

    const int tid  = threadIdx.x;
    const int lane = tid & 31, w = tid >> 5;
    const int wm   = w >> 2, wn = w & 3;
    const int qb   = gridDim.x - 1 - blockIdx.x;
    const int bh   = blockIdx.y;
    const int b    = bh >> 4, h = bh & (NHEAD - 1);
    const size_t rowbase = (size_t)b * TSEQ + (size_t)qb * 64;
    const size_t bbase   = (size_t)b * TSEQ;

    const int orow = tid >> 3;
    const int ocol = (tid & 7) * 16;
    float O[16];
#pragma unroll
    for (int i = 0; i < 16; i++) O[i] = 0.f;

    float m[4], l[4];
#pragma unroll
    for (int i = 0; i < 4; i++) { m[i] = -1e30f; l[i] = 0.f; }

    // kick off K/V prefetch for kb=0, then load Q synchronously (overlaps)
    prefetch_tile(Kh, Kl, Kh_g, Kl_g, bbase, h, tid);
    prefetch_tile(Vh, Vl, Vh_g, Vl_g, bbase, h, tid);

    for (int i = tid; i < 64 * 16; i += 512) {
        int r = i >> 4, c8 = (i & 15) * 8;
        *(float4*)&Qh[r * LDQ + c8] =
            *(const float4*)(Qh_g + (rowbase + r) * DMODEL + h * DHEAD + c8);
        *(float4*)&Ql[r * LDQ + c8] =
            *(const float4*)(Ql_g + (rowbase + r) * DMODEL + h * DHEAD + c8);
    }

    for (int kb = 0; kb <= qb; kb++) {
        __pipeline_wait_prior(0);
        __syncthreads();   // K/V (and Q on iter 0) visible; prev Ss consumed

        // ---- S = Q K^T (warp tile 16 x 16, 2 accumulators) ----
        {
            nvcuda::wmma::fragment<nvcuda::wmma::accumulator, 16, 16, 16, float> s0, s1;
            nvcuda::wmma::fill_fragment(s0, 0.0f);
            nvcuda::wmma::fill_fragment(s1, 0.0f);
#pragma unroll
            for (int k8 = 0; k8 < 8; k8++) {
                nvcuda::wmma::fragment<nvcuda::wmma::matrix_a, 16, 16, 16,
                    __nv_bfloat16, nvcuda::wmma::row_major> aH, aL;
                nvcuda::wmma::load_matrix_sync(aH, &Qh[(wm*16)*LDQ + k8*16], LDQ);
                nvcuda::wmma::load_matrix_sync(aL, &Ql[(wm*16)*LDQ + k8*16], LDQ);
                nvcuda::wmma::fragment<nvcuda::wmma::matrix_b, 16, 16, 16,
                    __nv_bfloat16, nvcuda::wmma::col_major> bHf, bLf;
                nvcuda::wmma::load_matrix_sync(bHf, &Kh[(wn*16)*LDQ + k8*16], LDQ);
                nvcuda::wmma::load_matrix_sync(bLf, &Kl[(wn*16)*LDQ + k8*16], LDQ);
                nvcuda::wmma::mma_sync(s0, aH, bHf, s0);
                nvcuda::wmma::mma_sync(s1, aL, bHf, s1);
                nvcuda::wmma::mma_sync(s0, aH, bLf, s0);
            }
#pragma unroll
            for (int t = 0; t < s0.num_elements; t++) s0.x[t] += s1.x[t];
            nvcuda::wmma::store_matrix_sync(&Ss[(wm*16)*SPF + wn*16], s0, SPF,
                                            nvcuda::wmma::mem_row_major);
        }
        __syncthreads();   // K consumed by all warps; Ss ready

        // prefetch next K while softmax/PV run
        if (kb < qb) {
            prefetch_tile(Kh, Kl, Kh_g, Kl_g, bbase + (size_t)(kb + 1) * 64, h, tid);
        }

        // ---- online softmax (warp w: rows w*4..w*4+3) ----
#pragma unroll
        for (int i = 0; i < 4; i++) {
            int r = w * 4 + i;
            int qglob = qb * 64 + r;
            int kg0 = kb * 64 + lane;
            float s0v = (kg0      <= qglob) ? Ss[r * SPF + lane]      : -1e30f;
            float s1v = (kg0 + 32 <= qglob) ? Ss[r * SPF + lane + 32] : -1e30f;
            float tmax = fmaxf(s0v, s1v);
#pragma unroll
            for (int off = 16; off; off >>= 1)
                tmax = fmaxf(tmax, __shfl_xor_sync(0xffffffffu, tmax, off));
            float mnew = fmaxf(m[i], tmax);
            float p0 = __expf(s0v - mnew);
            float p1 = __expf(s1v - mnew);
            float alpha = __expf(m[i] - mnew);
            float ps = p0 + p1;
#pragma unroll
            for (int off = 16; off; off >>= 1)
                ps += __shfl_xor_sync(0xffffffffu, ps, off);
            l[i] = l[i] * alpha + ps;
            m[i] = mnew;
            __nv_bfloat16 h0 = __float2bfloat16_rn(p0);
            __nv_bfloat16 h1 = __float2bfloat16_rn(p1);
            Ph[r * LDP + lane]      = h0;
            Ph[r * LDP + lane + 32] = h1;
            Pl[r * LDP + lane]      = __float2bfloat16_rn(p0 - __bfloat162float(h0));
            Pl[r * LDP + lane + 32] = __float2bfloat16_rn(p1 - __bfloat162float(h1));
            if (lane == 0) salpha[r] = alpha;
        }
        __syncthreads();   // P ready; Ss free for Ot

        // ---- Ot = P V (warp tile 16 x 32, 2 accumulator sets) ----
        {
            nvcuda::wmma::fragment<nvcuda::wmma::accumulator, 16, 16, 16, float> oA[2], oB[2];
#pragma unroll
            for (int j = 0; j < 2; j++) {
                nvcuda::wmma::fill_fragment(oA[j], 0.0f);
                nvcuda::wmma::fill_fragment(oB[j], 0.0f);
            }
#pragma unroll
            for (int k4 = 0; k4 < 4; k4++) {
                nvcuda::wmma::fragment<nvcuda::wmma::matrix_a, 16, 16, 16,
                    __nv_bfloat16, nvcuda::wmma::row_major> aH, aL;
                nvcuda::wmma::load_matrix_sync(aH, &Ph[(wm*16)*LDP + k4*16], LDP);
                nvcuda::wmma::load_matrix_sync(aL, &Pl[(wm*16)*LDP + k4*16], LDP);
#pragma unroll
                for (int j = 0; j < 2; j++) {
                    nvcuda::wmma::fragment<nvcuda::wmma::matrix_b, 16, 16, 16,
                        __nv_bfloat16, nvcuda::wmma::row_major> bHf, bLf;
                    nvcuda::wmma::load_matrix_sync(bHf,
                        &Vh[(k4*16)*LDQ + wn*32 + j*16], LDQ);
                    nvcuda::wmma::load_matrix_sync(bLf,
                        &Vl[(k4*16)*LDQ + wn*32 + j*16], LDQ);
                    nvcuda::wmma::mma_sync(oA[j], aH, bHf, oA[j]);
                    nvcuda::wmma::mma_sync(oB[j], aL, bHf, oB[j]);
                    nvcuda::wmma::mma_sync(oA[j], aH, bLf, oA[j]);
                }
            }
#pragma unroll
            for (int j = 0; j < 2; j++) {
#pragma unroll
                for (int t = 0; t < oA[j].num_elements; t++) oA[j].x[t] += oB[j].x[t];
                nvcuda::wmma::store_matrix_sync(
                    &Ss[(wm*16)*SPF + wn*32 + j*16], oA[j], SPF,
                    nvcuda::wmma::mem_row_major);
            }
        }
        __syncthreads();   // V consumed; Ot ready

        // prefetch next V while rescale runs
        if (kb < qb) {
            prefetch_tile(Vh, Vl, Vh_g, Vl_g, bbase + (size_t)(kb + 1) * 64, h, tid);
        }

        // ---- O = O*alpha + Ot ----
        {
            float a = salpha[orow];
#pragma unroll
            for (int j4 = 0; j4 < 4; j4++) {
                float4 t = *(float4*)&Ss[orow * SPF + ocol + j4 * 4];
                O[j4*4+0] = O[j4*4+0] * a + t.x;
                O[j4*4+1] = O[j4*4+1] * a + t.y;
                O[j4*4+2] = O[j4*4+2] * a + t.z;
                O[j4*4+3] = O[j4*4+3] * a + t.w;
            }
        }
    }

    if (lane == 0) {
#pragma unroll
        for (int i = 0; i < 4; i++) sl[w * 4 + i] = 1.0f / l[i];
    }
    __syncthreads();

    {
        float inv = sl[orow];
        size_t gbase = (rowbase + orow) * DMODEL + h * DHEAD + ocol;
#pragma unroll
        for (int j = 0; j < 8; j++) {
            float v0 = O[2*j]   * inv;
            float v1 = O[2*j+1] * inv;
            __nv_bfloat16 h0 = __float2bfloat16_rn(v0);
            __nv_bfloat16 h1 = __float2bfloat16_rn(v1);
            __nv_bfloat162 hp; hp.x = h0; hp.y = h1;
            __nv_bfloat162 lp;
            lp.x = __float2bfloat16_rn(v0 - __bfloat162float(h0));
            lp.y = __float2bfloat16_rn(v1 - __bfloat162float(h1));
            *(__nv_bfloat162*)(Chi + gbase + 2*j) = hp;
            *(__nv_bfloat162*)(Clo + gbase + 2*j) = lp;
        }
    }
}

// ---------------------------------------------------------------------------
extern "C" void kernel_launch(void* const* d_in, const int* in_sizes, int n_in,
                              void* d_out, int out_size)
{
    const float* x  = (const float*)d_in[0];
    const float* qw = (const float*)d_in[1];
    const float* kw = (const float*)d_in[2];
    const float* vw = (const float*)d_in[3];
    const float* ww = (const float*)d_in[4];
    const int* pos  = (const int*)d_in[5];
    float* out = (float*)d_out;

    float *Qb, *Kb, *Vb;
    cudaGetSymbolAddress((void**)&Qb, g_Q);
    cudaGetSymbolAddress((void**)&Kb, g_K);
    cudaGetSymbolAddress((void**)&Vb, g_V);

    __nv_bfloat16 *xhi, *xlo, *chi, *clo;
    __nv_bfloat16 *qh, *ql, *kh, *kl, *vh, *vl;
    __nv_bfloat16 *wqkvh, *wqkvl, *woh, *wol;
    cudaGetSymbolAddress((void**)&xhi, g_xhi);
    cudaGetSymbolAddress((void**)&xlo, g_xlo);
    cudaGetSymbolAddress((void**)&chi, g_chi);
    cudaGetSymbolAddress((void**)&clo, g_clo);
    cudaGetSymbolAddress((void**)&qh, g_qh);
    cudaGetSymbolAddress((void**)&ql, g_ql);
    cudaGetSymbolAddress((void**)&kh, g_kh);
    cudaGetSymbolAddress((void**)&kl, g_kl);
    cudaGetSymbolAddress((void**)&vh, g_vh);
    cudaGetSymbolAddress((void**)&vl, g_vl);
    cudaGetSymbolAddress((void**)&wqkvh, g_wqkvh);
    cudaGetSymbolAddress((void**)&wqkvl, g_wqkvl);
    cudaGetSymbolAddress((void**)&woh, g_wohi);
    cudaGetSymbolAddress((void**)&wol, g_wolo);

    const int xn4 = MTOT * DMODEL / 4;
    const int wn4 = DMODEL * DMODEL / 4;
    split_kernel<<<(xn4 + 255) / 256, 256>>>(x, xhi, xlo, xn4);
    split_pack_kernel<<<(wn4 + 255) / 256, 256>>>(qw, wqkvh, wqkvl, 0);
    split_pack_kernel<<<(wn4 + 255) / 256, 256>>>(kw, wqkvh, wqkvl, DMODEL);
    split_pack_kernel<<<(wn4 + 255) / 256, 256>>>(vw, wqkvh, wqkvl, 2*DMODEL);
    split_kernel<<<(wn4 + 255) / 256, 256>>>(ww, woh, wol, wn4);

    cudaFuncSetAttribute(qkv_gemm,
                         cudaFuncAttributeMaxDynamicSharedMemorySize, GEMM_SMEM);

    dim3 gq(NQKV / 256, MTOT / 128);
    qkv_gemm<<<gq, 256, GEMM_SMEM>>>(xhi, xlo, wqkvh, wqkvl,
                                     Qb, Kb, Vb, DMODEL, NQKV);

    int ropeN = 2 * BATCH * TSEQ * NHEAD * 64;
    rope_split_kernel<<<(ropeN + 255) / 256, 256>>>(Qb, Kb, qh, ql, kh, kl, pos);
    split_kernel<<<(xn4 + 255) / 256, 256>>>(Vb, vh, vl, xn4);

    cudaFuncSetAttribute(attn_mma_kernel,
                         cudaFuncAttributeMaxDynamicSharedMemorySize, ATT_SMEM);
    dim3 ga(TSEQ / 64, BATCH * NHEAD);
    attn_mma_kernel<<<ga, 512, ATT_SMEM>>>(qh, ql, kh, kl, vh, vl, chi, clo);

    dim3 go(DMODEL / 256, MTOT / 128);
    qkv_gemm<<<go, 256, GEMM_SMEM>>>(chi, clo, woh, wol,
                                     out, out, out, DMODEL, DMODEL);
}